// round 4
// baseline (speedup 1.0000x reference)
#include <cuda_runtime.h>
#include <cstdint>
#include <cstddef>

#define NN 2048
#define BB 8
#define TT 12
#define DD 64
#define BD  (BB*DD)        // 512
#define BTD (BB*TT*DD)     // 6144
#define ROWS (NN*BB)       // 16384

// ---------------- scratch (device globals; no allocs allowed) ----------------
__device__ float g_S2 [(size_t)NN*NN];    // 2A^2 - I
__device__ float g_xT [(size_t)NN*BTD];   // x transposed to [n][b][t][d]
__device__ float g_xd1[(size_t)NN*BTD];   // A  @ xT
__device__ float g_xd2[(size_t)NN*BTD];   // S2 @ xT
__device__ float g_h  [(size_t)NN*BD];    // state  [n][b][d]
__device__ float g_hd1[(size_t)NN*BD];
__device__ float g_hd2[(size_t)NN*BD];
__device__ float g_g  [(size_t)NN*BD];    // z * h
__device__ float g_gd1[(size_t)NN*BD];
__device__ float g_gd2[(size_t)NN*BD];
__device__ float g_r  [(size_t)NN*BD];    // r gate

// ---------------- layout helpers ----------------
// x (input) : [b][t][n][d]
// xT / xd*  : row = n*BB+b, within row: [t][d] (stride TT*DD per row)
// h / hd* / g / gd* / r : row = n*BB+b, within row: [d] (stride DD)

// ---------------- transpose x -> xT ----------------
__global__ void transpose_x_kernel(const float* __restrict__ x) {
    size_t i = (size_t)blockIdx.x * 256 + threadIdx.x;
    const size_t total = (size_t)BB*TT*NN*DD;
    if (i >= total) return;
    int d = (int)(i & 63);
    size_t q = i >> 6;           // (b*TT+t)*NN + n
    int n = (int)(q & (NN-1));
    q >>= 11;                    // b*TT + t
    int t = (int)(q % TT);
    int b = (int)(q / TT);
    g_xT[(((size_t)n*BB + b)*TT + t)*DD + d] = x[i];
}

__global__ void init_h_kernel(const float* __restrict__ h0) {
    size_t i = (size_t)blockIdx.x * 256 + threadIdx.x;   // over [b][n][d]
    const size_t total = (size_t)BB*NN*DD;
    if (i >= total) return;
    int d = (int)(i & 63);
    size_t q = i >> 6;           // b*NN + n
    int n = (int)(q & (NN-1));
    int b = (int)(q >> 11);
    g_h[((size_t)n*BB + b)*DD + d] = h0[i];
}

__global__ void write_last_kernel(float* __restrict__ out_last) {
    size_t i = (size_t)blockIdx.x * 256 + threadIdx.x;   // over [b][n][d]
    const size_t total = (size_t)BB*NN*DD;
    if (i >= total) return;
    int d = (int)(i & 63);
    size_t q = i >> 6;
    int n = (int)(q & (NN-1));
    int b = (int)(q >> 11);
    out_last[i] = g_h[((size_t)n*BB + b)*DD + d];
}

// ---------------- generic SGEMM: C[M,N] = A[M,K] @ B[K,N] ----------------
// MODE 0: plain   MODE 1: C = 2*acc - I  (for S2)
// BM=BN=64, BK=16, 128 threads, thread tile 8x4. All dims divide evenly.
template<int MODE>
__global__ __launch_bounds__(128)
void sgemm64(const float* __restrict__ A, const float* __restrict__ B,
             float* __restrict__ C, int M, int N, int K) {
    __shared__ float As[16][64];
    __shared__ float Bs[16][64];
    int tid  = threadIdx.x;
    int row0 = blockIdx.y << 6;
    int col0 = blockIdx.x << 6;
    int ty = tid >> 4;      // 0..7  -> rows ty*8
    int tx = tid & 15;      // 0..15 -> cols tx*4
    float acc[8][4] = {};

    for (int k0 = 0; k0 < K; k0 += 16) {
        #pragma unroll
        for (int i = 0; i < 2; i++) {
            int c = tid + (i << 7);           // 0..255 float4 chunks of A tile
            int r = c >> 2, c4 = (c & 3) << 2;
            float4 v = *(const float4*)&A[(size_t)(row0 + r)*K + k0 + c4];
            As[c4+0][r] = v.x; As[c4+1][r] = v.y;
            As[c4+2][r] = v.z; As[c4+3][r] = v.w;
        }
        #pragma unroll
        for (int i = 0; i < 2; i++) {
            int c = tid + (i << 7);
            int r = c >> 4, c4 = (c & 15) << 2;
            *(float4*)&Bs[r][c4] = *(const float4*)&B[(size_t)(k0 + r)*N + col0 + c4];
        }
        __syncthreads();
        #pragma unroll
        for (int k = 0; k < 16; k++) {
            float4 a0 = *(const float4*)&As[k][ty << 3];
            float4 a1 = *(const float4*)&As[k][(ty << 3) + 4];
            float4 bv = *(const float4*)&Bs[k][tx << 2];
            float a[8] = {a0.x,a0.y,a0.z,a0.w,a1.x,a1.y,a1.z,a1.w};
            float b[4] = {bv.x,bv.y,bv.z,bv.w};
            #pragma unroll
            for (int ii = 0; ii < 8; ii++)
                #pragma unroll
                for (int jj = 0; jj < 4; jj++)
                    acc[ii][jj] += a[ii] * b[jj];
        }
        __syncthreads();
    }
    #pragma unroll
    for (int ii = 0; ii < 8; ii++) {
        int r = row0 + (ty << 3) + ii;
        int c = col0 + (tx << 2);
        float4 v;
        v.x = acc[ii][0]; v.y = acc[ii][1]; v.z = acc[ii][2]; v.w = acc[ii][3];
        if (MODE == 1) {
            v.x = 2.f*v.x - ((r == c+0) ? 1.f : 0.f);
            v.y = 2.f*v.y - ((r == c+1) ? 1.f : 0.f);
            v.z = 2.f*v.z - ((r == c+2) ? 1.f : 0.f);
            v.w = 2.f*v.w - ((r == c+3) ? 1.f : 0.f);
        }
        *(float4*)&C[(size_t)r*N + c] = v;
    }
}

// ---------------- gate: zr = sigmoid([f6]@Wg + bg); g = z*h; store r ----------
// rows = n*BB+b (16384), cols = 128. K = 384 in 12 chunks of 32.
// chunk source order MUST match W_gate [K=3][2D=128][128] flattening:
//   k0:[x_t | h], k1:[xd1 | hd1], k2:[xd2 | hd2]
__global__ __launch_bounds__(256)
void gate_kernel(const float* __restrict__ Wg, const float* __restrict__ bg, int t) {
    __shared__ float Fs[32][68];    // [k][row], padded
    __shared__ float Ws[32][128];
    int tid  = threadIdx.x;
    int row0 = blockIdx.x << 6;     // 64 rows per block
    int ty = tid >> 4;              // 0..15 -> rows ty*4
    int tx = tid & 15;              // 0..15 -> cols tx*8
    float acc[4][8] = {};

    for (int kc = 0; kc < 12; kc++) {
        int s    = kc >> 1;
        int koff = (kc & 1) << 5;
        const float* src; size_t stride;
        switch (s) {
            case 0: src = g_xT  + (size_t)t*DD; stride = (size_t)TT*DD; break;
            case 1: src = g_h;                  stride = DD;            break;
            case 2: src = g_xd1 + (size_t)t*DD; stride = (size_t)TT*DD; break;
            case 3: src = g_hd1;                stride = DD;            break;
            case 4: src = g_xd2 + (size_t)t*DD; stride = (size_t)TT*DD; break;
            default:src = g_hd2;                stride = DD;            break;
        }
        #pragma unroll
        for (int i = 0; i < 8; i++) {
            int c = tid + (i << 8);           // 0..2047
            int k = c & 31, r = c >> 5;
            Fs[k][r] = src[(size_t)(row0 + r)*stride + koff + k];
        }
        #pragma unroll
        for (int i = 0; i < 4; i++) {
            int c  = tid + (i << 8);          // float4 id 0..1023
            int k  = c >> 5, o4 = (c & 31) << 2;
            *(float4*)&Ws[k][o4] = *(const float4*)&Wg[(size_t)(kc*32 + k)*128 + o4];
        }
        __syncthreads();
        #pragma unroll
        for (int k = 0; k < 32; k++) {
            float4 av = *(const float4*)&Fs[k][ty << 2];
            float4 w0 = *(const float4*)&Ws[k][tx << 3];
            float4 w1 = *(const float4*)&Ws[k][(tx << 3) + 4];
            float a[4] = {av.x, av.y, av.z, av.w};
            float w[8] = {w0.x,w0.y,w0.z,w0.w,w1.x,w1.y,w1.z,w1.w};
            #pragma unroll
            for (int ii = 0; ii < 4; ii++)
                #pragma unroll
                for (int jj = 0; jj < 8; jj++)
                    acc[ii][jj] += a[ii] * w[jj];
        }
        __syncthreads();
    }
    #pragma unroll
    for (int ii = 0; ii < 4; ii++) {
        int r = row0 + (ty << 2) + ii;
        #pragma unroll
        for (int jj = 0; jj < 8; jj++) {
            int o = (tx << 3) + jj;
            float v  = acc[ii][jj] + bg[o];
            float sg = 1.f / (1.f + expf(-v));
            if (o < 64) g_g[(size_t)r*DD + o]        = sg * g_h[(size_t)r*DD + o];
            else        g_r[(size_t)r*DD + (o - 64)] = sg;
        }
    }
}

// ---------------- cand: hc = tanh([f6]@Wc + bc); GRU update; residual out ----
// chunk order: k0:[x_t | g], k1:[xd1 | gd1], k2:[xd2 | gd2]
__global__ __launch_bounds__(256)
void cand_kernel(const float* __restrict__ Wc, const float* __restrict__ bc,
                 const float* __restrict__ x, float* __restrict__ out, int t) {
    __shared__ float Fs[32][68];
    __shared__ float Ws[32][64];
    int tid  = threadIdx.x;
    int row0 = blockIdx.x << 6;
    int ty = tid >> 4;              // rows ty*4
    int tx = tid & 15;              // cols tx*4
    float acc[4][4] = {};

    for (int kc = 0; kc < 12; kc++) {
        int s    = kc >> 1;
        int koff = (kc & 1) << 5;
        const float* src; size_t stride;
        switch (s) {
            case 0: src = g_xT  + (size_t)t*DD; stride = (size_t)TT*DD; break;
            case 1: src = g_g;                  stride = DD;            break;
            case 2: src = g_xd1 + (size_t)t*DD; stride = (size_t)TT*DD; break;
            case 3: src = g_gd1;                stride = DD;            break;
            case 4: src = g_xd2 + (size_t)t*DD; stride = (size_t)TT*DD; break;
            default:src = g_gd2;                stride = DD;            break;
        }
        #pragma unroll
        for (int i = 0; i < 8; i++) {
            int c = tid + (i << 8);
            int k = c & 31, r = c >> 5;
            Fs[k][r] = src[(size_t)(row0 + r)*stride + koff + k];
        }
        #pragma unroll
        for (int i = 0; i < 2; i++) {
            int c  = tid + (i << 8);          // float4 id 0..511
            int k  = c >> 4, o4 = (c & 15) << 2;
            *(float4*)&Ws[k][o4] = *(const float4*)&Wc[(size_t)(kc*32 + k)*64 + o4];
        }
        __syncthreads();
        #pragma unroll
        for (int k = 0; k < 32; k++) {
            float4 av = *(const float4*)&Fs[k][ty << 2];
            float4 wv = *(const float4*)&Ws[k][tx << 2];
            float a[4] = {av.x, av.y, av.z, av.w};
            float w[4] = {wv.x, wv.y, wv.z, wv.w};
            #pragma unroll
            for (int ii = 0; ii < 4; ii++)
                #pragma unroll
                for (int jj = 0; jj < 4; jj++)
                    acc[ii][jj] += a[ii] * w[jj];
        }
        __syncthreads();
    }
    #pragma unroll
    for (int ii = 0; ii < 4; ii++) {
        int r = row0 + (ty << 2) + ii;
        int n = r >> 3, b = r & 7;
        size_t xbase = (((size_t)b*TT + t)*NN + n)*DD;
        #pragma unroll
        for (int jj = 0; jj < 4; jj++) {
            int o = (tx << 2) + jj;
            float hc = tanhf(acc[ii][jj] + bc[o]);
            size_t idx = (size_t)r*DD + o;
            float rg  = g_r[idx];
            float h0v = g_h[idx];
            float hn  = rg * h0v + (1.f - rg) * hc;
            g_h[idx] = hn;                       // in-place: element owned by this thread
            out[xbase + o] = x[xbase + o] + hn;  // residual
        }
    }
}

// ---------------- launch ----------------
extern "C" void kernel_launch(void* const* d_in, const int* in_sizes, int n_in,
                              void* d_out, int out_size) {
    const float* x   = (const float*)d_in[0];
    const float* h0  = (const float*)d_in[1];
    const float* adj = (const float*)d_in[2];
    const float* Wg  = (const float*)d_in[3];
    const float* bg  = (const float*)d_in[4];
    const float* Wc  = (const float*)d_in[5];
    const float* bc  = (const float*)d_in[6];
    float* out = (float*)d_out;

    void *pS2, *pxT, *pxd1, *pxd2, *ph, *phd1, *phd2, *pg, *pgd1, *pgd2;
    cudaGetSymbolAddress(&pS2,  g_S2);
    cudaGetSymbolAddress(&pxT,  g_xT);
    cudaGetSymbolAddress(&pxd1, g_xd1);
    cudaGetSymbolAddress(&pxd2, g_xd2);
    cudaGetSymbolAddress(&ph,   g_h);
    cudaGetSymbolAddress(&phd1, g_hd1);
    cudaGetSymbolAddress(&phd2, g_hd2);
    cudaGetSymbolAddress(&pg,   g_g);
    cudaGetSymbolAddress(&pgd1, g_gd1);
    cudaGetSymbolAddress(&pgd2, g_gd2);

    const size_t total_x = (size_t)BB*TT*NN*DD;     // 12,582,912
    const size_t total_h = (size_t)BB*NN*DD;        // 1,048,576

    transpose_x_kernel<<<(int)((total_x + 255)/256), 256>>>(x);
    init_h_kernel<<<(int)((total_h + 255)/256), 256>>>(h0);

    // S2 = 2*A@A - I
    sgemm64<1><<<dim3(NN/64, NN/64), 128>>>(adj, adj, (float*)pS2, NN, NN, NN);
    // x diffusions (whole sequence at once)
    sgemm64<0><<<dim3(BTD/64, NN/64), 128>>>(adj,          (const float*)pxT, (float*)pxd1, NN, BTD, NN);
    sgemm64<0><<<dim3(BTD/64, NN/64), 128>>>((float*)pS2,  (const float*)pxT, (float*)pxd2, NN, BTD, NN);

    for (int t = 0; t < TT; t++) {
        sgemm64<0><<<dim3(BD/64, NN/64), 128>>>(adj,         (const float*)ph, (float*)phd1, NN, BD, NN);
        sgemm64<0><<<dim3(BD/64, NN/64), 128>>>((float*)pS2, (const float*)ph, (float*)phd2, NN, BD, NN);
        gate_kernel<<<ROWS/64, 256>>>(Wg, bg, t);
        sgemm64<0><<<dim3(BD/64, NN/64), 128>>>(adj,         (const float*)pg, (float*)pgd1, NN, BD, NN);
        sgemm64<0><<<dim3(BD/64, NN/64), 128>>>((float*)pS2, (const float*)pg, (float*)pgd2, NN, BD, NN);
        cand_kernel<<<ROWS/64, 256>>>(Wc, bc, x, out, t);
    }

    write_last_kernel<<<(int)((total_h + 255)/256), 256>>>(out + total_x);
}

// round 6
// speedup vs baseline: 2.4031x; 2.4031x over previous
#include <cuda_runtime.h>
#include <cuda_bf16.h>
#include <cstdint>
#include <cstddef>

typedef __nv_bfloat16 bf16;
#define NN 2048
#define BB 8
#define TT 12
#define DD 64
#define MX 6144
#define MH 512
static constexpr size_t MXN = (size_t)MX*NN;
static constexpr size_t MHN = (size_t)MH*NN;

// ---- float scratch offsets ----
static constexpr size_t O_XF=0, O_XD1F=O_XF+MXN, O_XD2F=O_XD1F+MXN, O_ST=O_XD2F+MXN,
 O_HF=O_ST+12*MHN, O_HD1F=O_HF+MHN, O_HD2F=O_HD1F+MHN, O_GF=O_HD2F+MHN,
 O_GD1F=O_GF+MHN, O_GD2F=O_GD1F+MHN, O_RF=O_GD2F+MHN, NFB=O_RF+MHN;
// ---- bf16 scratch offsets ----
static constexpr size_t B_AHI=0, B_ALO=B_AHI+(size_t)NN*NN, B_XHI=B_ALO+(size_t)NN*NN,
 B_XLO=B_XHI+MXN, B_XD1HI=B_XLO+MXN, B_XD1LO=B_XD1HI+MXN,
 B_HHI=B_XD1LO+MXN, B_HLO=B_HHI+MHN, B_HD1HI=B_HLO+MHN, B_HD1LO=B_HD1HI+MHN,
 B_GHI=B_HD1LO+MHN, B_GLO=B_GHI+MHN, B_GD1HI=B_GLO+MHN, B_GD1LO=B_GD1HI+MHN,
 NBB=B_GD1LO+MHN;

__device__ float g_fbuf[NFB];
__device__ bf16  g_bbuf[NBB];

// ---------------- helpers ----------------
__device__ __forceinline__ uint32_t smem_u32(const void* p){
    uint32_t a;
    asm("{ .reg .u64 t; cvta.to.shared.u64 t, %1; cvt.u32.u64 %0, t; }" : "=r"(a) : "l"(p));
    return a;
}
#define SWZ(x) ((x) ^ (((x) >> 3) & 0x70))

__device__ __forceinline__ void split1(float v, bf16* hp, bf16* lp){
    bf16 h = __float2bfloat16_rn(v);
    *hp = h; *lp = __float2bfloat16_rn(v - __bfloat162float(h));
}

__device__ __forceinline__ void ldsm4(uint32_t* r, uint32_t addr){
    asm volatile("ldmatrix.sync.aligned.m8n8.x4.shared.b16 {%0,%1,%2,%3}, [%4];"
        : "=r"(r[0]), "=r"(r[1]), "=r"(r[2]), "=r"(r[3]) : "r"(addr));
}
__device__ __forceinline__ void mma16816(float* c, const uint32_t* a, uint32_t b0, uint32_t b1){
    asm volatile("mma.sync.aligned.m16n8k16.row.col.f32.bf16.bf16.f32 "
        "{%0,%1,%2,%3}, {%4,%5,%6,%7}, {%8,%9}, {%0,%1,%2,%3};"
        : "+f"(c[0]), "+f"(c[1]), "+f"(c[2]), "+f"(c[3])
        : "r"(a[0]), "r"(a[1]), "r"(a[2]), "r"(a[3]), "r"(b0), "r"(b1));
}

// ---------------- diffusion GEMM: out[m][n] = sum_k act[m][k]*adj[n][k] ----------------
// bf16x3 split via K-extension: 96 chunks of 64 (terms hi*hi, lo*hi, hi*lo).
// CHAIN: outF = 2*D - base.  SPLIT: also write bf16 hi/lo of out.
template<int TM, int SPLIT, int CHAIN>
__global__ __launch_bounds__(256)
void diffuse_kernel(const bf16* __restrict__ aHi, const bf16* __restrict__ aLo,
                    float* __restrict__ outF, bf16* __restrict__ outHi,
                    bf16* __restrict__ outLo, const float* __restrict__ baseF)
{
    constexpr int NWN = (TM == 128) ? 2 : 4;     // warps along n
    constexpr int WN  = 128 / NWN;               // 64 or 32
    constexpr int NJ  = WN / 8;                  // 8 or 4
    constexpr int NJ2 = WN / 16;                 // 4 or 2
    constexpr int ABYTES = TM * 128;
    constexpr int STG = ABYTES + 128 * 128;

    extern __shared__ char smem[];
    uint32_t sb = smem_u32(smem);
    int tid = threadIdx.x, lane = tid & 31, wid = tid >> 5;
    int wm = wid / NWN, wn = wid % NWN;
    int m0 = blockIdx.y * TM, n0 = blockIdx.x << 7;

    const char* aH = (const char*)(aHi + (size_t)m0 * NN);
    const char* aL = (const char*)(aLo + (size_t)m0 * NN);
    const char* bH = (const char*)(g_bbuf + B_AHI + (size_t)n0 * NN);
    const char* bL = (const char*)(g_bbuf + B_ALO + (size_t)n0 * NN);

    auto load_chunk = [&](int kc, int stg){
        int term = kc >> 5;
        size_t ko = (size_t)((kc & 31) << 7);            // bytes within 4096B row
        const char* As = ((term == 1) ? aL : aH) + ko;   // hi, lo, hi
        const char* Bs = ((term == 2) ? bL : bH) + ko;   // hi, hi, lo
        uint32_t s = sb + stg * STG;
        #pragma unroll
        for (int i = 0; i < ABYTES/4096; i++){           // A: 16B per thread per iter
            int q = tid + (i << 8);
            int row = q >> 3, c = (q & 7) << 4;
            asm volatile("cp.async.cg.shared.global [%0], [%1], 16;"
                :: "r"(s + SWZ((uint32_t)(row*128 + c))), "l"(As + (size_t)row*4096 + c) : "memory");
        }
        #pragma unroll
        for (int i = 0; i < 4; i++){                     // B: 128 rows
            int q = tid + (i << 8);
            int row = q >> 3, c = (q & 7) << 4;
            asm volatile("cp.async.cg.shared.global [%0], [%1], 16;"
                :: "r"(s + ABYTES + SWZ((uint32_t)(row*128 + c))), "l"(Bs + (size_t)row*4096 + c) : "memory");
        }
    };

    float acc[2][NJ][4];
    #pragma unroll
    for (int i = 0; i < 2; i++)
        #pragma unroll
        for (int j = 0; j < NJ; j++)
            #pragma unroll
            for (int q = 0; q < 4; q++) acc[i][j][q] = 0.f;

    load_chunk(0, 0); asm volatile("cp.async.commit_group;" ::: "memory");
    load_chunk(1, 1); asm volatile("cp.async.commit_group;" ::: "memory");

    for (int kc = 0; kc < 96; kc++){
        int cur = kc % 3;
        if (kc + 2 < 96) load_chunk(kc + 2, (kc + 2) % 3);
        asm volatile("cp.async.commit_group;" ::: "memory");
        asm volatile("cp.async.wait_group 2;" ::: "memory");
        __syncthreads();
        uint32_t sA = sb + cur * STG, sB = sA + ABYTES;
        #pragma unroll
        for (int s = 0; s < 4; s++){
            int kb = s << 5;                              // byte offset of k16 step
            uint32_t af[2][4];
            #pragma unroll
            for (int i = 0; i < 2; i++){
                int row = wm*32 + i*16 + (lane & 7) + ((lane >> 3) & 1) * 8;
                int col = kb + ((lane >> 4) & 1) * 16;
                ldsm4(af[i], sA + SWZ((uint32_t)(row*128 + col)));
            }
            uint32_t bfm[NJ2][4];
            #pragma unroll
            for (int j2 = 0; j2 < NJ2; j2++){
                int row = wn*WN + j2*16 + (lane & 7) + ((lane >> 4) & 1) * 8;
                int col = kb + ((lane >> 3) & 1) * 16;
                ldsm4(bfm[j2], sB + SWZ((uint32_t)(row*128 + col)));
            }
            #pragma unroll
            for (int i = 0; i < 2; i++)
                #pragma unroll
                for (int j = 0; j < NJ; j++)
                    mma16816(acc[i][j], af[i], bfm[j>>1][(j&1)*2], bfm[j>>1][(j&1)*2+1]);
        }
        __syncthreads();
    }

    // epilogue: fragment (i,j): rows m0+wm*32+i*16+{lane>>2, +8}, cols n0+wn*WN+j*8+(lane&3)*2
    #pragma unroll
    for (int i = 0; i < 2; i++){
        int rowb = m0 + wm*32 + i*16 + (lane >> 2);
        #pragma unroll
        for (int j = 0; j < NJ; j++){
            int col = n0 + wn*WN + j*8 + (lane & 3)*2;
            #pragma unroll
            for (int h = 0; h < 2; h++){
                int row = rowb + h*8;
                size_t off = (size_t)row * NN + col;
                float2 v; v.x = acc[i][j][h*2]; v.y = acc[i][j][h*2+1];
                if (CHAIN){
                    float2 b2 = *(const float2*)&baseF[off];
                    v.x = 2.f*v.x - b2.x; v.y = 2.f*v.y - b2.y;
                }
                *(float2*)&outF[off] = v;
                if (SPLIT){
                    union {bf16 b[2]; uint32_t u;} H, L;
                    split1(v.x, &H.b[0], &L.b[0]);
                    split1(v.y, &H.b[1], &L.b[1]);
                    *(uint32_t*)&outHi[off] = H.u;
                    *(uint32_t*)&outLo[off] = L.u;
                }
            }
        }
    }
}

// ---------------- prep kernels ----------------
__global__ __launch_bounds__(256) void prep_adj_kernel(const float* __restrict__ adj){
    size_t i = ((size_t)blockIdx.x * 256 + threadIdx.x) * 4;
    float4 v = *(const float4*)&adj[i];
    union {bf16 b[4]; uint2 u;} H, L;
    split1(v.x,&H.b[0],&L.b[0]); split1(v.y,&H.b[1],&L.b[1]);
    split1(v.z,&H.b[2],&L.b[2]); split1(v.w,&H.b[3],&L.b[3]);
    *(uint2*)&g_bbuf[B_AHI + i] = H.u;
    *(uint2*)&g_bbuf[B_ALO + i] = L.u;
}

// transpose [row][n][d] -> feature-major [row*64+d][n], with optional bf16 split
template<int SPLIT>
__global__ __launch_bounds__(256)
void prep_T_kernel(const float* __restrict__ src, float* __restrict__ dstF,
                   bf16* __restrict__ dstH, bf16* __restrict__ dstL){
    __shared__ float S[64][65];
    int n0 = blockIdx.x << 6, rr = blockIdx.y;
    const float* sp = src + ((size_t)rr * NN + n0) * DD;
    #pragma unroll
    for (int i = 0; i < 16; i++){
        int q = threadIdx.x + (i << 8);
        S[q >> 6][q & 63] = sp[(size_t)(q >> 6) * DD + (q & 63)];
    }
    __syncthreads();
    #pragma unroll
    for (int i = 0; i < 16; i++){
        int q = threadIdx.x + (i << 8);
        int d = q >> 6, nl = q & 63;
        float v = S[nl][d];
        size_t off = ((size_t)rr * DD + d) * NN + n0 + nl;
        dstF[off] = v;
        if (SPLIT){ bf16 h; split1(v, &h, &dstL[off]); dstH[off] = h; }
    }
}

// ---------------- gate: zr = sigmoid(W^T F + b); g = z*h (+split); r stored ----------------
__global__ __launch_bounds__(256)
void gate_kernel(const float* __restrict__ Wg, const float* __restrict__ bg, int t){
    __shared__ float Fs[32][128];
    __shared__ float Ws[32][128];
    int tid = threadIdx.x, n0 = blockIdx.x << 7, b = blockIdx.y;
    int ty = tid >> 4, tx = tid & 15;          // o=ty*8, n=tx*8
    float acc[8][8] = {};
    const float* srcs[6] = {
        g_fbuf + O_XF   + ((size_t)(b*TT + t))*DD*NN,
        g_fbuf + O_HF   + (size_t)b*DD*NN,
        g_fbuf + O_XD1F + ((size_t)(b*TT + t))*DD*NN,
        g_fbuf + O_HD1F + (size_t)b*DD*NN,
        g_fbuf + O_XD2F + ((size_t)(b*TT + t))*DD*NN,
        g_fbuf + O_HD2F + (size_t)b*DD*NN };
    for (int kc = 0; kc < 12; kc++){
        const float* src = srcs[kc >> 1] + (size_t)((kc & 1) << 5)*NN;
        #pragma unroll
        for (int i = 0; i < 4; i++){
            int id = tid + (i << 8);
            int k = id >> 5, c4 = (id & 31) << 2;
            *(float4*)&Fs[k][c4] = *(const float4*)&src[(size_t)k*NN + n0 + c4];
            *(float4*)&Ws[k][c4] = *(const float4*)&Wg[(size_t)(kc*32 + k)*128 + c4];
        }
        __syncthreads();
        #pragma unroll
        for (int k = 0; k < 32; k++){
            float4 w0 = *(const float4*)&Ws[k][ty << 3];
            float4 w1 = *(const float4*)&Ws[k][(ty << 3) + 4];
            float4 f0 = *(const float4*)&Fs[k][tx << 3];
            float4 f1 = *(const float4*)&Fs[k][(tx << 3) + 4];
            float w[8] = {w0.x,w0.y,w0.z,w0.w,w1.x,w1.y,w1.z,w1.w};
            float f[8] = {f0.x,f0.y,f0.z,f0.w,f1.x,f1.y,f1.z,f1.w};
            #pragma unroll
            for (int oi = 0; oi < 8; oi++)
                #pragma unroll
                for (int ni = 0; ni < 8; ni++) acc[oi][ni] += w[oi]*f[ni];
        }
        __syncthreads();
    }
    #pragma unroll
    for (int oi = 0; oi < 8; oi++){
        int o = (ty << 3) + oi;
        float bv = bg[o];
        #pragma unroll
        for (int ni = 0; ni < 8; ni++){
            int n = n0 + (tx << 3) + ni;
            float sg = 1.f / (1.f + expf(-(acc[oi][ni] + bv)));
            if (o < 64){
                size_t idx = ((size_t)b*DD + o)*NN + n;
                float gv = sg * g_fbuf[O_HF + idx];
                g_fbuf[O_GF + idx] = gv;
                bf16 h; split1(gv, &h, &g_bbuf[B_GLO + idx]); g_bbuf[B_GHI + idx] = h;
            } else {
                g_fbuf[O_RF + ((size_t)b*DD + (o - 64))*NN + n] = sg;
            }
        }
    }
}

// ---------------- cand: hc = tanh(...); h = r*h + (1-r)*hc; store h(+split)+states ----------------
__global__ __launch_bounds__(256)
void cand_kernel(const float* __restrict__ Wc, const float* __restrict__ bc, int t){
    __shared__ float Fs[32][128];
    __shared__ float Ws[32][64];
    int tid = threadIdx.x, n0 = blockIdx.x << 7, b = blockIdx.y;
    int ty = tid >> 5, tx = tid & 31;           // o=ty*8, n=tx*4
    float acc[8][4] = {};
    const float* srcs[6] = {
        g_fbuf + O_XF   + ((size_t)(b*TT + t))*DD*NN,
        g_fbuf + O_GF   + (size_t)b*DD*NN,
        g_fbuf + O_XD1F + ((size_t)(b*TT + t))*DD*NN,
        g_fbuf + O_GD1F + (size_t)b*DD*NN,
        g_fbuf + O_XD2F + ((size_t)(b*TT + t))*DD*NN,
        g_fbuf + O_GD2F + (size_t)b*DD*NN };
    for (int kc = 0; kc < 12; kc++){
        const float* src = srcs[kc >> 1] + (size_t)((kc & 1) << 5)*NN;
        #pragma unroll
        for (int i = 0; i < 4; i++){
            int id = tid + (i << 8);
            int k = id >> 5, c4 = (id & 31) << 2;
            *(float4*)&Fs[k][c4] = *(const float4*)&src[(size_t)k*NN + n0 + c4];
        }
        #pragma unroll
        for (int i = 0; i < 2; i++){
            int id = tid + (i << 8);
            int k = id >> 4, c4 = (id & 15) << 2;
            *(float4*)&Ws[k][c4] = *(const float4*)&Wc[(size_t)(kc*32 + k)*64 + c4];
        }
        __syncthreads();
        #pragma unroll
        for (int k = 0; k < 32; k++){
            float4 w0 = *(const float4*)&Ws[k][ty << 3];
            float4 w1 = *(const float4*)&Ws[k][(ty << 3) + 4];
            float4 fv = *(const float4*)&Fs[k][tx << 2];
            float w[8] = {w0.x,w0.y,w0.z,w0.w,w1.x,w1.y,w1.z,w1.w};
            float f[4] = {fv.x,fv.y,fv.z,fv.w};
            #pragma unroll
            for (int oi = 0; oi < 8; oi++)
                #pragma unroll
                for (int ni = 0; ni < 4; ni++) acc[oi][ni] += w[oi]*f[ni];
        }
        __syncthreads();
    }
    #pragma unroll
    for (int oi = 0; oi < 8; oi++){
        int o = (ty << 3) + oi;
        float bv = bc[o];
        #pragma unroll
        for (int ni = 0; ni < 4; ni++){
            int n = n0 + (tx << 2) + ni;
            size_t idx = ((size_t)b*DD + o)*NN + n;
            float hc = tanhf(acc[oi][ni] + bv);
            float r = g_fbuf[O_RF + idx];
            float hn = r * g_fbuf[O_HF + idx] + (1.f - r) * hc;
            g_fbuf[O_HF + idx] = hn;
            bf16 h; split1(hn, &h, &g_bbuf[B_HLO + idx]); g_bbuf[B_HHI + idx] = h;
            g_fbuf[O_ST + (size_t)t*MHN + idx] = hn;
        }
    }
}

// ---------------- output assembly ----------------
__global__ __launch_bounds__(256)
void final_out_kernel(const float* __restrict__ x, float* __restrict__ out){
    __shared__ float S[64][65];
    int n0 = blockIdx.x << 6, bt = blockIdx.y;
    int b = bt / TT, t = bt % TT;
    const float* st = g_fbuf + O_ST + (size_t)t*MHN + (size_t)b*DD*NN;
    #pragma unroll
    for (int i = 0; i < 16; i++){
        int q = threadIdx.x + (i << 8);
        int d = q >> 6, nl = q & 63;
        S[d][nl] = st[(size_t)d*NN + n0 + nl];
    }
    __syncthreads();
    #pragma unroll
    for (int i = 0; i < 16; i++){
        int q = threadIdx.x + (i << 8);
        int nl = q >> 6, d = q & 63;
        size_t off = ((size_t)bt*NN + n0 + nl)*DD + d;
        out[off] = x[off] + S[d][nl];
    }
}

__global__ __launch_bounds__(256)
void last_out_kernel(float* __restrict__ outL){
    __shared__ float S[64][65];
    int n0 = blockIdx.x << 6, b = blockIdx.y;
    const float* hp = g_fbuf + O_HF + (size_t)b*DD*NN;
    #pragma unroll
    for (int i = 0; i < 16; i++){
        int q = threadIdx.x + (i << 8);
        int d = q >> 6, nl = q & 63;
        S[d][nl] = hp[(size_t)d*NN + n0 + nl];
    }
    __syncthreads();
    #pragma unroll
    for (int i = 0; i < 16; i++){
        int q = threadIdx.x + (i << 8);
        int nl = q >> 6, d = q & 63;
        outL[((size_t)b*NN + n0 + nl)*DD + d] = S[d][nl];
    }
}

// ---------------- launch ----------------
extern "C" void kernel_launch(void* const* d_in, const int* in_sizes, int n_in,
                              void* d_out, int out_size) {
    const float* x   = (const float*)d_in[0];
    const float* h0  = (const float*)d_in[1];
    const float* adj = (const float*)d_in[2];
    const float* Wg  = (const float*)d_in[3];
    const float* bg  = (const float*)d_in[4];
    const float* Wc  = (const float*)d_in[5];
    const float* bc  = (const float*)d_in[6];
    float* out = (float*)d_out;

    void *pf, *pb;
    cudaGetSymbolAddress(&pf, g_fbuf);
    cudaGetSymbolAddress(&pb, g_bbuf);
    float* F = (float*)pf;
    bf16*  B = (bf16*)pb;

    const int SM128 = 3 * (128*128 + 128*128);   // 98304
    const int SM64  = 3 * (64*128 + 128*128);    // 73728
    cudaFuncSetAttribute(diffuse_kernel<128,1,0>, cudaFuncAttributeMaxDynamicSharedMemorySize, SM128);
    cudaFuncSetAttribute(diffuse_kernel<128,0,1>, cudaFuncAttributeMaxDynamicSharedMemorySize, SM128);
    cudaFuncSetAttribute(diffuse_kernel<64,1,0>,  cudaFuncAttributeMaxDynamicSharedMemorySize, SM64);
    cudaFuncSetAttribute(diffuse_kernel<64,0,1>,  cudaFuncAttributeMaxDynamicSharedMemorySize, SM64);

    prep_adj_kernel<<<(NN*NN)/1024, 256>>>(adj);
    prep_T_kernel<1><<<dim3(NN/64, BB*TT), 256>>>(x,  F+O_XF, B+B_XHI, B+B_XLO);
    prep_T_kernel<1><<<dim3(NN/64, BB),    256>>>(h0, F+O_HF, B+B_HHI, B+B_HLO);

    // xd1 = A @ x ; xd2 = 2*A@xd1 - x
    diffuse_kernel<128,1,0><<<dim3(16,48),256,SM128>>>(B+B_XHI,  B+B_XLO,  F+O_XD1F, B+B_XD1HI, B+B_XD1LO, nullptr);
    diffuse_kernel<128,0,1><<<dim3(16,48),256,SM128>>>(B+B_XD1HI,B+B_XD1LO,F+O_XD2F, nullptr,  nullptr,   F+O_XF);

    for (int t = 0; t < TT; t++){
        diffuse_kernel<64,1,0><<<dim3(16,8),256,SM64>>>(B+B_HHI,  B+B_HLO,  F+O_HD1F, B+B_HD1HI, B+B_HD1LO, nullptr);
        diffuse_kernel<64,0,1><<<dim3(16,8),256,SM64>>>(B+B_HD1HI,B+B_HD1LO,F+O_HD2F, nullptr,  nullptr,   F+O_HF);
        gate_kernel<<<dim3(16,8),256>>>(Wg, bg, t);
        diffuse_kernel<64,1,0><<<dim3(16,8),256,SM64>>>(B+B_GHI,  B+B_GLO,  F+O_GD1F, B+B_GD1HI, B+B_GD1LO, nullptr);
        diffuse_kernel<64,0,1><<<dim3(16,8),256,SM64>>>(B+B_GD1HI,B+B_GD1LO,F+O_GD2F, nullptr,  nullptr,   F+O_GF);
        cand_kernel<<<dim3(16,8),256>>>(Wc, bc, t);
    }

    final_out_kernel<<<dim3(NN/64, BB*TT), 256>>>(x, out);
    last_out_kernel<<<dim3(NN/64, BB), 256>>>(out + MXN);
}

// round 7
// speedup vs baseline: 2.9751x; 1.2380x over previous
#include <cuda_runtime.h>
#include <cstdint>
#include <cstddef>

#define NN 2048
#define BB 8
#define TT 12
#define DD 64
#define MX 6144
#define MH 512
static constexpr size_t MXN = (size_t)MX*NN;
static constexpr size_t MHN = (size_t)MH*NN;

// ---- exact fp32 scratch offsets ----
static constexpr size_t O_XF=0, O_XD1F=O_XF+MXN, O_XD2F=O_XD1F+MXN, O_ST=O_XD2F+MXN,
 O_HF=O_ST+12*MHN, O_HD1F=O_HF+MHN, O_HD2F=O_HD1F+MHN, O_GF=O_HD2F+MHN,
 O_GD1F=O_GF+MHN, O_GD2F=O_GD1F+MHN, O_RF=O_GD2F+MHN, NFB=O_RF+MHN;
// ---- tf32-rounded operand scratch offsets ----
static constexpr size_t T_A=0, T_X=T_A+(size_t)NN*NN, T_XD1=T_X+MXN,
 T_H=T_XD1+MXN, T_HD1=T_H+MHN, T_G=T_HD1+MHN, T_GD1=T_G+MHN, NTB=T_GD1+MHN;

__device__ float g_fbuf[NFB];
__device__ float g_tbuf[NTB];

// ---------------- helpers ----------------
__device__ __forceinline__ uint32_t smem_u32(const void* p){
    uint32_t a;
    asm("{ .reg .u64 t; cvta.to.shared.u64 t, %1; cvt.u32.u64 %0, t; }" : "=r"(a) : "l"(p));
    return a;
}
#define SWZ(x) ((x) ^ (((x) >> 3) & 0x70))

__device__ __forceinline__ float tf32r(float v){
    uint32_t r; asm("cvt.rna.tf32.f32 %0, %1;" : "=r"(r) : "f"(v));
    return __uint_as_float(r);
}
__device__ __forceinline__ uint32_t lds_u(uint32_t a){
    uint32_t v; asm volatile("ld.shared.b32 %0, [%1];" : "=r"(v) : "r"(a)); return v;
}
__device__ __forceinline__ void mma1688(float* c, const uint32_t* a, uint32_t b0, uint32_t b1){
    asm volatile("mma.sync.aligned.m16n8k8.row.col.f32.tf32.tf32.f32 "
        "{%0,%1,%2,%3}, {%4,%5,%6,%7}, {%8,%9}, {%0,%1,%2,%3};"
        : "+f"(c[0]), "+f"(c[1]), "+f"(c[2]), "+f"(c[3])
        : "r"(a[0]), "r"(a[1]), "r"(a[2]), "r"(a[3]), "r"(b0), "r"(b1));
}

// ---------------- diffusion GEMM (tf32): out[m][n] = sum_k act[m][k]*adj[n][k] ----------------
// K = 2048 in 64 chunks of 32 floats (128B rows). CHAIN: outF = 2*D - base. SPLIT: also tf32 out.
template<int TM, int SPLIT, int CHAIN>
__global__ __launch_bounds__(256)
void diffuse_kernel(const float* __restrict__ actT, float* __restrict__ outF,
                    float* __restrict__ outT, const float* __restrict__ baseF)
{
    constexpr int NWN = (TM == 128) ? 2 : 4;   // warps along n
    constexpr int WN  = 128 / NWN;             // 64 or 32
    constexpr int NJ  = WN / 8;                // 8 or 4
    constexpr int ABYTES = TM * 128;
    constexpr int STG = ABYTES + 128 * 128;

    extern __shared__ char smem[];
    uint32_t sb = smem_u32(smem);
    int tid = threadIdx.x, lane = tid & 31, wid = tid >> 5;
    int wm = wid / NWN, wn = wid % NWN;
    int m0 = blockIdx.y * TM, n0 = blockIdx.x << 7;

    const char* aT = (const char*)(actT + (size_t)m0 * NN);
    const char* bT = (const char*)(g_tbuf + T_A + (size_t)n0 * NN);

    auto load_chunk = [&](int kc, int stg){
        const char* As = aT + (size_t)kc * 128;
        const char* Bs = bT + (size_t)kc * 128;
        uint32_t s = sb + stg * STG;
        #pragma unroll
        for (int i = 0; i < ABYTES/4096; i++){
            int q = tid + (i << 8);
            int row = q >> 3, c = (q & 7) << 4;
            asm volatile("cp.async.cg.shared.global [%0], [%1], 16;"
                :: "r"(s + SWZ((uint32_t)(row*128 + c))), "l"(As + (size_t)row*8192 + c) : "memory");
        }
        #pragma unroll
        for (int i = 0; i < 4; i++){
            int q = tid + (i << 8);
            int row = q >> 3, c = (q & 7) << 4;
            asm volatile("cp.async.cg.shared.global [%0], [%1], 16;"
                :: "r"(s + ABYTES + SWZ((uint32_t)(row*128 + c))), "l"(Bs + (size_t)row*8192 + c) : "memory");
        }
    };

    float acc[2][NJ][4];
    #pragma unroll
    for (int i = 0; i < 2; i++)
        #pragma unroll
        for (int j = 0; j < NJ; j++)
            #pragma unroll
            for (int q = 0; q < 4; q++) acc[i][j][q] = 0.f;

    load_chunk(0, 0); asm volatile("cp.async.commit_group;" ::: "memory");
    load_chunk(1, 1); asm volatile("cp.async.commit_group;" ::: "memory");

    for (int kc = 0; kc < 64; kc++){
        int cur = kc % 3;
        if (kc + 2 < 64) load_chunk(kc + 2, (kc + 2) % 3);
        asm volatile("cp.async.commit_group;" ::: "memory");
        asm volatile("cp.async.wait_group 2;" ::: "memory");
        __syncthreads();
        uint32_t sA = sb + cur * STG, sB = sA + ABYTES;
        #pragma unroll
        for (int s = 0; s < 4; s++){
            uint32_t c0 = (uint32_t)(s*32 + ((lane & 3) << 2));
            uint32_t af[2][4];
            #pragma unroll
            for (int i = 0; i < 2; i++){
                int row = wm*32 + i*16 + (lane >> 2);
                af[i][0] = lds_u(sA + SWZ((uint32_t)(row*128)     + c0));
                af[i][1] = lds_u(sA + SWZ((uint32_t)((row+8)*128) + c0));
                af[i][2] = lds_u(sA + SWZ((uint32_t)(row*128)     + c0 + 16));
                af[i][3] = lds_u(sA + SWZ((uint32_t)((row+8)*128) + c0 + 16));
            }
            #pragma unroll
            for (int j = 0; j < NJ; j++){
                int n = wn*WN + j*8 + (lane >> 2);
                uint32_t b0 = lds_u(sB + SWZ((uint32_t)(n*128) + c0));
                uint32_t b1 = lds_u(sB + SWZ((uint32_t)(n*128) + c0 + 16));
                mma1688(acc[0][j], af[0], b0, b1);
                mma1688(acc[1][j], af[1], b0, b1);
            }
        }
        __syncthreads();
    }

    // epilogue: fragment (i,j): rows m0+wm*32+i*16+{lane>>2, +8}, cols n0+wn*WN+j*8+(lane&3)*2
    #pragma unroll
    for (int i = 0; i < 2; i++){
        int rowb = m0 + wm*32 + i*16 + (lane >> 2);
        #pragma unroll
        for (int j = 0; j < NJ; j++){
            int col = n0 + wn*WN + j*8 + (lane & 3)*2;
            #pragma unroll
            for (int h = 0; h < 2; h++){
                int row = rowb + h*8;
                size_t off = (size_t)row * NN + col;
                float2 v; v.x = acc[i][j][h*2]; v.y = acc[i][j][h*2+1];
                if (CHAIN){
                    float2 b2 = *(const float2*)&baseF[off];
                    v.x = 2.f*v.x - b2.x; v.y = 2.f*v.y - b2.y;
                }
                *(float2*)&outF[off] = v;
                if (SPLIT){
                    float2 t; t.x = tf32r(v.x); t.y = tf32r(v.y);
                    *(float2*)&outT[off] = t;
                }
            }
        }
    }
}

// ---------------- prep kernels ----------------
__global__ __launch_bounds__(256) void prep_adj_kernel(const float* __restrict__ adj){
    size_t i = ((size_t)blockIdx.x * 256 + threadIdx.x) * 4;
    float4 v = *(const float4*)&adj[i];
    float4 t; t.x = tf32r(v.x); t.y = tf32r(v.y); t.z = tf32r(v.z); t.w = tf32r(v.w);
    *(float4*)&g_tbuf[T_A + i] = t;
}

// transpose [row][n][d] (d contig) -> feature-major [row*64+d][n]: exact + tf32-rounded
__global__ __launch_bounds__(256)
void prep_T_kernel(const float* __restrict__ src, float* __restrict__ dstF,
                   float* __restrict__ dstT){
    __shared__ float S[64][65];
    int n0 = blockIdx.x << 6, rr = blockIdx.y;
    const float* sp = src + ((size_t)rr * NN + n0) * DD;
    #pragma unroll
    for (int i = 0; i < 16; i++){
        int q = threadIdx.x + (i << 8);
        S[q >> 6][q & 63] = sp[(size_t)(q >> 6) * DD + (q & 63)];
    }
    __syncthreads();
    #pragma unroll
    for (int i = 0; i < 16; i++){
        int q = threadIdx.x + (i << 8);
        int d = q >> 6, nl = q & 63;
        float v = S[nl][d];
        size_t off = ((size_t)rr * DD + d) * NN + n0 + nl;
        dstF[off] = v;
        dstT[off] = tf32r(v);
    }
}

// ---------------- gate: zr = sigmoid(W^T F + b); g = z*h (+tf32); r stored ----------------
__global__ __launch_bounds__(256)
void gate_kernel(const float* __restrict__ Wg, const float* __restrict__ bg, int t){
    __shared__ float Fs[32][128];
    __shared__ float Ws[32][128];
    int tid = threadIdx.x, n0 = blockIdx.x << 7, b = blockIdx.y;
    int ty = tid >> 4, tx = tid & 15;          // o=ty*8, n=tx*8
    float acc[8][8] = {};
    const float* srcs[6] = {
        g_fbuf + O_XF   + ((size_t)(b*TT + t))*DD*NN,
        g_fbuf + O_HF   + (size_t)b*DD*NN,
        g_fbuf + O_XD1F + ((size_t)(b*TT + t))*DD*NN,
        g_fbuf + O_HD1F + (size_t)b*DD*NN,
        g_fbuf + O_XD2F + ((size_t)(b*TT + t))*DD*NN,
        g_fbuf + O_HD2F + (size_t)b*DD*NN };
    for (int kc = 0; kc < 12; kc++){
        const float* src = srcs[kc >> 1] + (size_t)((kc & 1) << 5)*NN;
        #pragma unroll
        for (int i = 0; i < 4; i++){
            int id = tid + (i << 8);
            int k = id >> 5, c4 = (id & 31) << 2;
            *(float4*)&Fs[k][c4] = *(const float4*)&src[(size_t)k*NN + n0 + c4];
            *(float4*)&Ws[k][c4] = *(const float4*)&Wg[(size_t)(kc*32 + k)*128 + c4];
        }
        __syncthreads();
        #pragma unroll
        for (int k = 0; k < 32; k++){
            float4 w0 = *(const float4*)&Ws[k][ty << 3];
            float4 w1 = *(const float4*)&Ws[k][(ty << 3) + 4];
            float4 f0 = *(const float4*)&Fs[k][tx << 3];
            float4 f1 = *(const float4*)&Fs[k][(tx << 3) + 4];
            float w[8] = {w0.x,w0.y,w0.z,w0.w,w1.x,w1.y,w1.z,w1.w};
            float f[8] = {f0.x,f0.y,f0.z,f0.w,f1.x,f1.y,f1.z,f1.w};
            #pragma unroll
            for (int oi = 0; oi < 8; oi++)
                #pragma unroll
                for (int ni = 0; ni < 8; ni++) acc[oi][ni] += w[oi]*f[ni];
        }
        __syncthreads();
    }
    #pragma unroll
    for (int oi = 0; oi < 8; oi++){
        int o = (ty << 3) + oi;
        float bv = bg[o];
        #pragma unroll
        for (int ni = 0; ni < 8; ni++){
            int n = n0 + (tx << 3) + ni;
            float sg = 1.f / (1.f + expf(-(acc[oi][ni] + bv)));
            if (o < 64){
                size_t idx = ((size_t)b*DD + o)*NN + n;
                float gv = sg * g_fbuf[O_HF + idx];
                g_fbuf[O_GF + idx] = gv;
                g_tbuf[T_G + idx] = tf32r(gv);
            } else {
                g_fbuf[O_RF + ((size_t)b*DD + (o - 64))*NN + n] = sg;
            }
        }
    }
}

// ---------------- cand: hc = tanh(...); h = r*h + (1-r)*hc; store h(+tf32)+states ----------------
__global__ __launch_bounds__(256)
void cand_kernel(const float* __restrict__ Wc, const float* __restrict__ bc, int t){
    __shared__ float Fs[32][128];
    __shared__ float Ws[32][64];
    int tid = threadIdx.x, n0 = blockIdx.x << 7, b = blockIdx.y;
    int ty = tid >> 5, tx = tid & 31;           // o=ty*8, n=tx*4
    float acc[8][4] = {};
    const float* srcs[6] = {
        g_fbuf + O_XF   + ((size_t)(b*TT + t))*DD*NN,
        g_fbuf + O_GF   + (size_t)b*DD*NN,
        g_fbuf + O_XD1F + ((size_t)(b*TT + t))*DD*NN,
        g_fbuf + O_GD1F + (size_t)b*DD*NN,
        g_fbuf + O_XD2F + ((size_t)(b*TT + t))*DD*NN,
        g_fbuf + O_GD2F + (size_t)b*DD*NN };
    for (int kc = 0; kc < 12; kc++){
        const float* src = srcs[kc >> 1] + (size_t)((kc & 1) << 5)*NN;
        #pragma unroll
        for (int i = 0; i < 4; i++){
            int id = tid + (i << 8);
            int k = id >> 5, c4 = (id & 31) << 2;
            *(float4*)&Fs[k][c4] = *(const float4*)&src[(size_t)k*NN + n0 + c4];
        }
        #pragma unroll
        for (int i = 0; i < 2; i++){
            int id = tid + (i << 8);
            int k = id >> 4, c4 = (id & 15) << 2;
            *(float4*)&Ws[k][c4] = *(const float4*)&Wc[(size_t)(kc*32 + k)*64 + c4];
        }
        __syncthreads();
        #pragma unroll
        for (int k = 0; k < 32; k++){
            float4 w0 = *(const float4*)&Ws[k][ty << 3];
            float4 w1 = *(const float4*)&Ws[k][(ty << 3) + 4];
            float4 fv = *(const float4*)&Fs[k][tx << 2];
            float w[8] = {w0.x,w0.y,w0.z,w0.w,w1.x,w1.y,w1.z,w1.w};
            float f[4] = {fv.x,fv.y,fv.z,fv.w};
            #pragma unroll
            for (int oi = 0; oi < 8; oi++)
                #pragma unroll
                for (int ni = 0; ni < 4; ni++) acc[oi][ni] += w[oi]*f[ni];
        }
        __syncthreads();
    }
    #pragma unroll
    for (int oi = 0; oi < 8; oi++){
        int o = (ty << 3) + oi;
        float bv = bc[o];
        #pragma unroll
        for (int ni = 0; ni < 4; ni++){
            int n = n0 + (tx << 2) + ni;
            size_t idx = ((size_t)b*DD + o)*NN + n;
            float hc = tanhf(acc[oi][ni] + bv);
            float r = g_fbuf[O_RF + idx];
            float hn = r * g_fbuf[O_HF + idx] + (1.f - r) * hc;
            g_fbuf[O_HF + idx] = hn;
            g_tbuf[T_H + idx] = tf32r(hn);
            g_fbuf[O_ST + (size_t)t*MHN + idx] = hn;
        }
    }
}

// ---------------- output assembly ----------------
__global__ __launch_bounds__(256)
void final_out_kernel(const float* __restrict__ x, float* __restrict__ out){
    __shared__ float S[64][65];
    int n0 = blockIdx.x << 6, bt = blockIdx.y;
    int b = bt / TT, t = bt % TT;
    const float* st = g_fbuf + O_ST + (size_t)t*MHN + (size_t)b*DD*NN;
    #pragma unroll
    for (int i = 0; i < 16; i++){
        int q = threadIdx.x + (i << 8);
        int d = q >> 6, nl = q & 63;
        S[d][nl] = st[(size_t)d*NN + n0 + nl];
    }
    __syncthreads();
    #pragma unroll
    for (int i = 0; i < 16; i++){
        int q = threadIdx.x + (i << 8);
        int nl = q >> 6, d = q & 63;
        size_t off = ((size_t)bt*NN + n0 + nl)*DD + d;
        out[off] = x[off] + S[d][nl];
    }
}

__global__ __launch_bounds__(256)
void last_out_kernel(float* __restrict__ outL){
    __shared__ float S[64][65];
    int n0 = blockIdx.x << 6, b = blockIdx.y;
    const float* hp = g_fbuf + O_HF + (size_t)b*DD*NN;
    #pragma unroll
    for (int i = 0; i < 16; i++){
        int q = threadIdx.x + (i << 8);
        int d = q >> 6, nl = q & 63;
        S[d][nl] = hp[(size_t)d*NN + n0 + nl];
    }
    __syncthreads();
    #pragma unroll
    for (int i = 0; i < 16; i++){
        int q = threadIdx.x + (i << 8);
        int nl = q >> 6, d = q & 63;
        outL[((size_t)b*NN + n0 + nl)*DD + d] = S[d][nl];
    }
}

// ---------------- launch ----------------
extern "C" void kernel_launch(void* const* d_in, const int* in_sizes, int n_in,
                              void* d_out, int out_size) {
    const float* x   = (const float*)d_in[0];
    const float* h0  = (const float*)d_in[1];
    const float* adj = (const float*)d_in[2];
    const float* Wg  = (const float*)d_in[3];
    const float* bg  = (const float*)d_in[4];
    const float* Wc  = (const float*)d_in[5];
    const float* bc  = (const float*)d_in[6];
    float* out = (float*)d_out;

    void *pf, *pt;
    cudaGetSymbolAddress(&pf, g_fbuf);
    cudaGetSymbolAddress(&pt, g_tbuf);
    float* F = (float*)pf;
    float* T = (float*)pt;

    const int SM128 = 3 * (128*128 + 128*128);   // 98304
    const int SM64  = 3 * (64*128 + 128*128);    // 73728
    cudaFuncSetAttribute(diffuse_kernel<128,1,0>, cudaFuncAttributeMaxDynamicSharedMemorySize, SM128);
    cudaFuncSetAttribute(diffuse_kernel<128,0,1>, cudaFuncAttributeMaxDynamicSharedMemorySize, SM128);
    cudaFuncSetAttribute(diffuse_kernel<64,1,0>,  cudaFuncAttributeMaxDynamicSharedMemorySize, SM64);
    cudaFuncSetAttribute(diffuse_kernel<64,0,1>,  cudaFuncAttributeMaxDynamicSharedMemorySize, SM64);

    prep_adj_kernel<<<(NN*NN)/1024, 256>>>(adj);
    prep_T_kernel<<<dim3(NN/64, BB*TT), 256>>>(x,  F+O_XF, T+T_X);
    prep_T_kernel<<<dim3(NN/64, BB),    256>>>(h0, F+O_HF, T+T_H);

    // xd1 = A @ x ; xd2 = 2*A@xd1 - x
    diffuse_kernel<128,1,0><<<dim3(16,48),256,SM128>>>(T+T_X,   F+O_XD1F, T+T_XD1, nullptr);
    diffuse_kernel<128,0,1><<<dim3(16,48),256,SM128>>>(T+T_XD1, F+O_XD2F, nullptr, F+O_XF);

    for (int t = 0; t < TT; t++){
        diffuse_kernel<64,1,0><<<dim3(16,8),256,SM64>>>(T+T_H,   F+O_HD1F, T+T_HD1, nullptr);
        diffuse_kernel<64,0,1><<<dim3(16,8),256,SM64>>>(T+T_HD1, F+O_HD2F, nullptr, F+O_HF);
        gate_kernel<<<dim3(16,8),256>>>(Wg, bg, t);
        diffuse_kernel<64,1,0><<<dim3(16,8),256,SM64>>>(T+T_G,   F+O_GD1F, T+T_GD1, nullptr);
        diffuse_kernel<64,0,1><<<dim3(16,8),256,SM64>>>(T+T_GD1, F+O_GD2F, nullptr, F+O_GF);
        cand_kernel<<<dim3(16,8),256>>>(Wc, bc, t);
    }

    final_out_kernel<<<dim3(NN/64, BB*TT), 256>>>(x, out);
    last_out_kernel<<<dim3(NN/64, BB), 256>>>(out + MXN);
}

// round 8
// speedup vs baseline: 3.1559x; 1.0608x over previous
#include <cuda_runtime.h>
#include <cstdint>
#include <cstddef>

#define NN 2048
#define BB 8
#define TT 12
#define DD 64
#define MX 6144
#define MH 512
static constexpr size_t MXN = (size_t)MX*NN;
static constexpr size_t MHN = (size_t)MH*NN;
static constexpr size_t NN2 = (size_t)NN*NN;

// ---- exact fp32 scratch offsets ----
static constexpr size_t O_XF=0, O_XD1F=O_XF+MXN, O_XD2F=O_XD1F+MXN, O_ST=O_XD2F+MXN,
 O_HF=O_ST+12*MHN, O_HD1F=O_HF+MHN, O_HD2F=O_HD1F+MHN, O_GF=O_HD2F+MHN,
 O_GD1F=O_GF+MHN, O_GD2F=O_GD1F+MHN, O_RF=O_GD2F+MHN, NFB=O_RF+MHN;
// ---- tf32-rounded operand scratch offsets (T_S2 MUST follow T_A: stacked B) ----
static constexpr size_t T_A=0, T_S2=T_A+NN2, T_AT=T_S2+NN2, T_X=T_AT+NN2,
 T_H=T_X+MXN, T_G=T_H+MHN, NTB=T_G+MHN;

__device__ float g_fbuf[NFB];
__device__ float g_tbuf[NTB];

// ---------------- helpers ----------------
__device__ __forceinline__ uint32_t smem_u32(const void* p){
    uint32_t a;
    asm("{ .reg .u64 t; cvta.to.shared.u64 t, %1; cvt.u32.u64 %0, t; }" : "=r"(a) : "l"(p));
    return a;
}
#define SWZ(x) ((x) ^ (((x) >> 3) & 0x70))

__device__ __forceinline__ float tf32r(float v){
    uint32_t r; asm("cvt.rna.tf32.f32 %0, %1;" : "=r"(r) : "f"(v));
    return __uint_as_float(r);
}
__device__ __forceinline__ uint32_t lds_u(uint32_t a){
    uint32_t v; asm volatile("ld.shared.b32 %0, [%1];" : "=r"(v) : "r"(a)); return v;
}
__device__ __forceinline__ void mma1688(float* c, const uint32_t* a, uint32_t b0, uint32_t b1){
    asm volatile("mma.sync.aligned.m16n8k8.row.col.f32.tf32.tf32.f32 "
        "{%0,%1,%2,%3}, {%4,%5,%6,%7}, {%8,%9}, {%0,%1,%2,%3};"
        : "+f"(c[0]), "+f"(c[1]), "+f"(c[2]), "+f"(c[3])
        : "r"(a[0]), "r"(a[1]), "r"(a[2]), "r"(a[3]), "r"(b0), "r"(b1));
}

// ---------------- diffusion GEMM (tf32): out[m][n] = sum_k act[m][k] * B[n][k] ----------------
// TM=128, TN=128, K=2048 in 64 chunks of 32 floats. 4-stage cp.async pipeline, 1 sync/chunk.
// S2M=0: dual fp32 outputs (n<NN -> out1, else out2 at n-NN).  S2M=1: out1 = tf32(2*v - I).
template<int S2M>
__global__ __launch_bounds__(256)
void diffuse_kernel(const float* __restrict__ actT, const float* __restrict__ bTp,
                    float* __restrict__ out1, float* __restrict__ out2)
{
    constexpr int TM = 128;
    constexpr int WN = 64, NJ = 8;               // 8 warps: wm=wid>>1 (4), wn=wid&1 (2)
    constexpr int ABYTES = TM * 128;             // 16KB
    constexpr int STG = ABYTES + 16384;          // 32KB/stage
    extern __shared__ char smem[];
    uint32_t sb = smem_u32(smem);
    int tid = threadIdx.x, lane = tid & 31, wid = tid >> 5;
    int wm = wid >> 1, wn = wid & 1;
    int m0 = blockIdx.y * TM, n0 = blockIdx.x << 7;

    const char* aT = (const char*)(actT + (size_t)m0 * NN);
    const char* bT = (const char*)(bTp  + (size_t)n0 * NN);

    auto load_chunk = [&](int kc, int stg){
        const char* As = aT + (size_t)kc * 128;
        const char* Bs = bT + (size_t)kc * 128;
        uint32_t s = sb + stg * STG;
        #pragma unroll
        for (int i = 0; i < 4; i++){
            int q = tid + (i << 8);
            int row = q >> 3, c = (q & 7) << 4;
            asm volatile("cp.async.cg.shared.global [%0], [%1], 16;"
                :: "r"(s + SWZ((uint32_t)(row*128 + c))), "l"(As + (size_t)row*8192 + c) : "memory");
        }
        #pragma unroll
        for (int i = 0; i < 4; i++){
            int q = tid + (i << 8);
            int row = q >> 3, c = (q & 7) << 4;
            asm volatile("cp.async.cg.shared.global [%0], [%1], 16;"
                :: "r"(s + ABYTES + SWZ((uint32_t)(row*128 + c))), "l"(Bs + (size_t)row*8192 + c) : "memory");
        }
    };

    float acc[2][NJ][4];
    #pragma unroll
    for (int i = 0; i < 2; i++)
        #pragma unroll
        for (int j = 0; j < NJ; j++)
            #pragma unroll
            for (int q = 0; q < 4; q++) acc[i][j][q] = 0.f;

    load_chunk(0, 0); asm volatile("cp.async.commit_group;" ::: "memory");
    load_chunk(1, 1); asm volatile("cp.async.commit_group;" ::: "memory");
    load_chunk(2, 2); asm volatile("cp.async.commit_group;" ::: "memory");

    for (int kc = 0; kc < 64; kc++){
        asm volatile("cp.async.wait_group 2;" ::: "memory");
        __syncthreads();
        uint32_t sA = sb + (kc & 3) * STG, sB = sA + ABYTES;

        uint32_t af[2][2][4];     // [buf][i][frag]
        uint32_t bfr[2][NJ][2];   // [buf][j][frag]
        auto load_frags = [&](int s, int buf){
            uint32_t c0 = (uint32_t)(s*32 + ((lane & 3) << 2));
            #pragma unroll
            for (int i = 0; i < 2; i++){
                int row = wm*32 + i*16 + (lane >> 2);
                af[buf][i][0] = lds_u(sA + SWZ((uint32_t)(row*128)     + c0));
                af[buf][i][1] = lds_u(sA + SWZ((uint32_t)((row+8)*128) + c0));
                af[buf][i][2] = lds_u(sA + SWZ((uint32_t)(row*128)     + c0 + 16));
                af[buf][i][3] = lds_u(sA + SWZ((uint32_t)((row+8)*128) + c0 + 16));
            }
            #pragma unroll
            for (int j = 0; j < NJ; j++){
                int n = wn*WN + j*8 + (lane >> 2);
                bfr[buf][j][0] = lds_u(sB + SWZ((uint32_t)(n*128) + c0));
                bfr[buf][j][1] = lds_u(sB + SWZ((uint32_t)(n*128) + c0 + 16));
            }
        };

        load_frags(0, 0);
        #pragma unroll
        for (int s = 0; s < 4; s++){
            if (s < 3) load_frags(s + 1, (s + 1) & 1);
            int b = s & 1;
            #pragma unroll
            for (int j = 0; j < NJ; j++){
                mma1688(acc[0][j], af[b][0], bfr[b][j][0], bfr[b][j][1]);
                mma1688(acc[1][j], af[b][1], bfr[b][j][0], bfr[b][j][1]);
            }
        }
        if (kc + 3 < 64) load_chunk(kc + 3, (kc + 3) & 3);
        asm volatile("cp.async.commit_group;" ::: "memory");
    }

    // epilogue: fragment (i,j): rows m0+wm*32+i*16+{lane>>2,+8}, cols wn*64+j*8+(lane&3)*2
    float* o; int cb;
    if (S2M){ o = out1; cb = n0; }
    else if (n0 < NN){ o = out1; cb = n0; }
    else { o = out2; cb = n0 - NN; }
    #pragma unroll
    for (int i = 0; i < 2; i++){
        int rowb = m0 + wm*32 + i*16 + (lane >> 2);
        #pragma unroll
        for (int j = 0; j < NJ; j++){
            int col = cb + wn*WN + j*8 + (lane & 3)*2;
            #pragma unroll
            for (int h = 0; h < 2; h++){
                int row = rowb + h*8;
                size_t off = (size_t)row * NN + col;
                float2 v; v.x = acc[i][j][h*2]; v.y = acc[i][j][h*2+1];
                if (S2M){
                    v.x = tf32r(2.f*v.x - ((row == col)   ? 1.f : 0.f));
                    v.y = tf32r(2.f*v.y - ((row == col+1) ? 1.f : 0.f));
                }
                *(float2*)&o[off] = v;
            }
        }
    }
}

// ---------------- prep kernels ----------------
__global__ __launch_bounds__(256) void prep_adj_kernel(const float* __restrict__ adj){
    size_t i = ((size_t)blockIdx.x * 256 + threadIdx.x) * 4;
    float4 v = *(const float4*)&adj[i];
    float4 t; t.x = tf32r(v.x); t.y = tf32r(v.y); t.z = tf32r(v.z); t.w = tf32r(v.w);
    *(float4*)&g_tbuf[T_A + i] = t;
}

__global__ __launch_bounds__(256) void prep_adjT_kernel(const float* __restrict__ adj){
    __shared__ float S[32][33];
    int x0 = blockIdx.x << 5, y0 = blockIdx.y << 5;
    int tx = threadIdx.x & 31, ty = threadIdx.x >> 5;   // 32 x 8
    #pragma unroll
    for (int i = 0; i < 4; i++)
        S[ty + i*8][tx] = adj[(size_t)(y0 + ty + i*8)*NN + x0 + tx];
    __syncthreads();
    #pragma unroll
    for (int i = 0; i < 4; i++)
        g_tbuf[T_AT + (size_t)(x0 + ty + i*8)*NN + y0 + tx] = tf32r(S[tx][ty + i*8]);
}

// transpose [row][n][d] (d contig) -> feature-major [row*64+d][n]: exact fp32 + tf32
__global__ __launch_bounds__(256)
void prep_T_kernel(const float* __restrict__ src, float* __restrict__ dstF,
                   float* __restrict__ dstT){
    __shared__ float S[64][65];
    int n0 = blockIdx.x << 6, rr = blockIdx.y;
    const float* sp = src + ((size_t)rr * NN + n0) * DD;
    #pragma unroll
    for (int i = 0; i < 16; i++){
        int q = threadIdx.x + (i << 8);
        S[q >> 6][q & 63] = sp[(size_t)(q >> 6) * DD + (q & 63)];
    }
    __syncthreads();
    #pragma unroll
    for (int i = 0; i < 16; i++){
        int q = threadIdx.x + (i << 8);
        int d = q >> 6, nl = q & 63;
        float v = S[nl][d];
        size_t off = ((size_t)rr * DD + d) * NN + n0 + nl;
        dstF[off] = v;
        dstT[off] = tf32r(v);
    }
}

// ---------------- gate: zr = sigmoid(W^T F + b); g = z*h (+tf32); r stored ----------------
__global__ __launch_bounds__(256)
void gate_kernel(const float* __restrict__ Wg, const float* __restrict__ bg, int t){
    __shared__ float Fs[32][128];
    __shared__ float Ws[32][128];
    int tid = threadIdx.x, n0 = blockIdx.x << 7, b = blockIdx.y;
    int ty = tid >> 4, tx = tid & 15;          // o=ty*8, n=tx*8
    float acc[8][8] = {};
    const float* srcs[6] = {
        g_fbuf + O_XF   + ((size_t)(b*TT + t))*DD*NN,
        g_fbuf + O_HF   + (size_t)b*DD*NN,
        g_fbuf + O_XD1F + ((size_t)(b*TT + t))*DD*NN,
        g_fbuf + O_HD1F + (size_t)b*DD*NN,
        g_fbuf + O_XD2F + ((size_t)(b*TT + t))*DD*NN,
        g_fbuf + O_HD2F + (size_t)b*DD*NN };
    for (int kc = 0; kc < 12; kc++){
        const float* src = srcs[kc >> 1] + (size_t)((kc & 1) << 5)*NN;
        #pragma unroll
        for (int i = 0; i < 4; i++){
            int id = tid + (i << 8);
            int k = id >> 5, c4 = (id & 31) << 2;
            *(float4*)&Fs[k][c4] = *(const float4*)&src[(size_t)k*NN + n0 + c4];
            *(float4*)&Ws[k][c4] = *(const float4*)&Wg[(size_t)(kc*32 + k)*128 + c4];
        }
        __syncthreads();
        #pragma unroll
        for (int k = 0; k < 32; k++){
            float4 w0 = *(const float4*)&Ws[k][ty << 3];
            float4 w1 = *(const float4*)&Ws[k][(ty << 3) + 4];
            float4 f0 = *(const float4*)&Fs[k][tx << 3];
            float4 f1 = *(const float4*)&Fs[k][(tx << 3) + 4];
            float w[8] = {w0.x,w0.y,w0.z,w0.w,w1.x,w1.y,w1.z,w1.w};
            float f[8] = {f0.x,f0.y,f0.z,f0.w,f1.x,f1.y,f1.z,f1.w};
            #pragma unroll
            for (int oi = 0; oi < 8; oi++)
                #pragma unroll
                for (int ni = 0; ni < 8; ni++) acc[oi][ni] += w[oi]*f[ni];
        }
        __syncthreads();
    }
    #pragma unroll
    for (int oi = 0; oi < 8; oi++){
        int o = (ty << 3) + oi;
        float bv = bg[o];
        #pragma unroll
        for (int ni = 0; ni < 8; ni++){
            int n = n0 + (tx << 3) + ni;
            float sg = 1.f / (1.f + expf(-(acc[oi][ni] + bv)));
            if (o < 64){
                size_t idx = ((size_t)b*DD + o)*NN + n;
                float gv = sg * g_fbuf[O_HF + idx];
                g_fbuf[O_GF + idx] = gv;
                g_tbuf[T_G + idx] = tf32r(gv);
            } else {
                g_fbuf[O_RF + ((size_t)b*DD + (o - 64))*NN + n] = sg;
            }
        }
    }
}

// ---------------- cand: hc = tanh(...); h = r*h + (1-r)*hc; store h(+tf32)+states ----------------
__global__ __launch_bounds__(256)
void cand_kernel(const float* __restrict__ Wc, const float* __restrict__ bc, int t){
    __shared__ float Fs[32][128];
    __shared__ float Ws[32][64];
    int tid = threadIdx.x, n0 = blockIdx.x << 7, b = blockIdx.y;
    int ty = tid >> 5, tx = tid & 31;           // o=ty*8, n=tx*4
    float acc[8][4] = {};
    const float* srcs[6] = {
        g_fbuf + O_XF   + ((size_t)(b*TT + t))*DD*NN,
        g_fbuf + O_GF   + (size_t)b*DD*NN,
        g_fbuf + O_XD1F + ((size_t)(b*TT + t))*DD*NN,
        g_fbuf + O_GD1F + (size_t)b*DD*NN,
        g_fbuf + O_XD2F + ((size_t)(b*TT + t))*DD*NN,
        g_fbuf + O_GD2F + (size_t)b*DD*NN };
    for (int kc = 0; kc < 12; kc++){
        const float* src = srcs[kc >> 1] + (size_t)((kc & 1) << 5)*NN;
        #pragma unroll
        for (int i = 0; i < 4; i++){
            int id = tid + (i << 8);
            int k = id >> 5, c4 = (id & 31) << 2;
            *(float4*)&Fs[k][c4] = *(const float4*)&src[(size_t)k*NN + n0 + c4];
        }
        #pragma unroll
        for (int i = 0; i < 2; i++){
            int id = tid + (i << 8);
            int k = id >> 4, c4 = (id & 15) << 2;
            *(float4*)&Ws[k][c4] = *(const float4*)&Wc[(size_t)(kc*32 + k)*64 + c4];
        }
        __syncthreads();
        #pragma unroll
        for (int k = 0; k < 32; k++){
            float4 w0 = *(const float4*)&Ws[k][ty << 3];
            float4 w1 = *(const float4*)&Ws[k][(ty << 3) + 4];
            float4 fv = *(const float4*)&Fs[k][tx << 2];
            float w[8] = {w0.x,w0.y,w0.z,w0.w,w1.x,w1.y,w1.z,w1.w};
            float f[4] = {fv.x,fv.y,fv.z,fv.w};
            #pragma unroll
            for (int oi = 0; oi < 8; oi++)
                #pragma unroll
                for (int ni = 0; ni < 4; ni++) acc[oi][ni] += w[oi]*f[ni];
        }
        __syncthreads();
    }
    #pragma unroll
    for (int oi = 0; oi < 8; oi++){
        int o = (ty << 3) + oi;
        float bv = bc[o];
        #pragma unroll
        for (int ni = 0; ni < 4; ni++){
            int n = n0 + (tx << 2) + ni;
            size_t idx = ((size_t)b*DD + o)*NN + n;
            float hc = tanhf(acc[oi][ni] + bv);
            float r = g_fbuf[O_RF + idx];
            float hn = r * g_fbuf[O_HF + idx] + (1.f - r) * hc;
            g_fbuf[O_HF + idx] = hn;
            g_tbuf[T_H + idx] = tf32r(hn);
            g_fbuf[O_ST + (size_t)t*MHN + idx] = hn;
        }
    }
}

// ---------------- output assembly ----------------
__global__ __launch_bounds__(256)
void final_out_kernel(const float* __restrict__ x, float* __restrict__ out){
    __shared__ float S[64][65];
    int n0 = blockIdx.x << 6, bt = blockIdx.y;
    int b = bt / TT, t = bt % TT;
    const float* st = g_fbuf + O_ST + (size_t)t*MHN + (size_t)b*DD*NN;
    #pragma unroll
    for (int i = 0; i < 16; i++){
        int q = threadIdx.x + (i << 8);
        int d = q >> 6, nl = q & 63;
        S[d][nl] = st[(size_t)d*NN + n0 + nl];
    }
    __syncthreads();
    #pragma unroll
    for (int i = 0; i < 16; i++){
        int q = threadIdx.x + (i << 8);
        int nl = q >> 6, d = q & 63;
        size_t off = ((size_t)bt*NN + n0 + nl)*DD + d;
        out[off] = x[off] + S[d][nl];
    }
}

__global__ __launch_bounds__(256)
void last_out_kernel(float* __restrict__ outL){
    __shared__ float S[64][65];
    int n0 = blockIdx.x << 6, b = blockIdx.y;
    const float* hp = g_fbuf + O_HF + (size_t)b*DD*NN;
    #pragma unroll
    for (int i = 0; i < 16; i++){
        int q = threadIdx.x + (i << 8);
        int d = q >> 6, nl = q & 63;
        S[d][nl] = hp[(size_t)d*NN + n0 + nl];
    }
    __syncthreads();
    #pragma unroll
    for (int i = 0; i < 16; i++){
        int q = threadIdx.x + (i << 8);
        int nl = q >> 6, d = q & 63;
        outL[((size_t)b*NN + n0 + nl)*DD + d] = S[d][nl];
    }
}

// ---------------- launch ----------------
extern "C" void kernel_launch(void* const* d_in, const int* in_sizes, int n_in,
                              void* d_out, int out_size) {
    const float* x   = (const float*)d_in[0];
    const float* h0  = (const float*)d_in[1];
    const float* adj = (const float*)d_in[2];
    const float* Wg  = (const float*)d_in[3];
    const float* bg  = (const float*)d_in[4];
    const float* Wc  = (const float*)d_in[5];
    const float* bc  = (const float*)d_in[6];
    float* out = (float*)d_out;

    void *pf, *pt;
    cudaGetSymbolAddress(&pf, g_fbuf);
    cudaGetSymbolAddress(&pt, g_tbuf);
    float* F = (float*)pf;
    float* T = (float*)pt;

    const int DSM = 4 * (128*128 + 128*128);   // 131072 bytes (4 stages x 32KB)
    cudaFuncSetAttribute(diffuse_kernel<0>, cudaFuncAttributeMaxDynamicSharedMemorySize, DSM);
    cudaFuncSetAttribute(diffuse_kernel<1>, cudaFuncAttributeMaxDynamicSharedMemorySize, DSM);

    prep_adj_kernel<<<(int)(NN2/1024), 256>>>(adj);
    prep_adjT_kernel<<<dim3(NN/32, NN/32), 256>>>(adj);
    prep_T_kernel<<<dim3(NN/64, BB*TT), 256>>>(x,  F+O_XF, T+T_X);
    prep_T_kernel<<<dim3(NN/64, BB),    256>>>(h0, F+O_HF, T+T_H);

    // S2' = tf32(2*A@A - I): act=A', B=A'^T  (written contiguously after T_A -> stacked [A';S2'])
    diffuse_kernel<1><<<dim3(16,16),256,DSM>>>(T+T_A, T+T_AT, T+T_S2, nullptr);

    // x diffusions vs stacked [A';S2']: one launch, outputs split to XD1F / XD2F
    diffuse_kernel<0><<<dim3(32,48),256,DSM>>>(T+T_X, T+T_A, F+O_XD1F, F+O_XD2F);

    for (int t = 0; t < TT; t++){
        diffuse_kernel<0><<<dim3(32,4),256,DSM>>>(T+T_H, T+T_A, F+O_HD1F, F+O_HD2F);
        gate_kernel<<<dim3(16,8),256>>>(Wg, bg, t);
        diffuse_kernel<0><<<dim3(32,4),256,DSM>>>(T+T_G, T+T_A, F+O_GD1F, F+O_GD2F);
        cand_kernel<<<dim3(16,8),256>>>(Wc, bc, t);
    }

    final_out_kernel<<<dim3(NN/64, BB*TT), 256>>>(x, out);
    last_out_kernel<<<dim3(NN/64, BB), 256>>>(out + MXN);
}

// round 9
// speedup vs baseline: 4.0691x; 1.2894x over previous
#include <cuda_runtime.h>
#include <cstdint>
#include <cstddef>

#define NN 2048
#define BB 8
#define TT 12
#define DD 64
#define MX 6144
#define MH 512
static constexpr size_t MXN = (size_t)MX*NN;
static constexpr size_t MHN = (size_t)MH*NN;
static constexpr size_t NN2 = (size_t)NN*NN;

// ---- exact fp32 scratch ----
static constexpr size_t O_ST=0, O_HF=O_ST+12*MHN, O_RF=O_HF+MHN, NFB=O_RF+MHN;
// ---- tf32-rounded scratch (T_S2 MUST follow T_A: stacked [A';S2']) ----
static constexpr size_t T_A=0, T_S2=T_A+NN2, T_AT=T_S2+NN2, T_X=T_AT+NN2,
 T_XD1=T_X+MXN, T_XD2=T_XD1+MXN,
 T_H=T_XD2+MXN, T_HD1=T_H+MHN, T_HD2=T_HD1+MHN,
 T_G=T_HD2+MHN, T_GD1=T_G+MHN, T_GD2=T_GD1+MHN,
 T_WG=T_GD2+MHN, T_WC=T_WG+384*128, NTB=T_WC+384*64;

__device__ float g_fbuf[NFB];
__device__ float g_tbuf[NTB];

// ---------------- helpers ----------------
__device__ __forceinline__ uint32_t smem_u32(const void* p){
    uint32_t a;
    asm("{ .reg .u64 t; cvta.to.shared.u64 t, %1; cvt.u32.u64 %0, t; }" : "=r"(a) : "l"(p));
    return a;
}
#define SWZ(x) ((x) ^ (((x) >> 3) & 0x70))

__device__ __forceinline__ float tf32r(float v){
    uint32_t r; asm("cvt.rna.tf32.f32 %0, %1;" : "=r"(r) : "f"(v));
    return __uint_as_float(r);
}
__device__ __forceinline__ uint32_t lds_u(uint32_t a){
    uint32_t v; asm volatile("ld.shared.b32 %0, [%1];" : "=r"(v) : "r"(a)); return v;
}
__device__ __forceinline__ void cpa16(uint32_t d, const void* s){
    asm volatile("cp.async.cg.shared.global [%0], [%1], 16;" :: "r"(d), "l"(s) : "memory");
}
__device__ __forceinline__ void mma1688(float* c, const uint32_t* a, uint32_t b0, uint32_t b1){
    asm volatile("mma.sync.aligned.m16n8k8.row.col.f32.tf32.tf32.f32 "
        "{%0,%1,%2,%3}, {%4,%5,%6,%7}, {%8,%9}, {%0,%1,%2,%3};"
        : "+f"(c[0]), "+f"(c[1]), "+f"(c[2]), "+f"(c[3])
        : "r"(a[0]), "r"(a[1]), "r"(a[2]), "r"(a[3]), "r"(b0), "r"(b1));
}

// ---------------- diffusion GEMM (tf32): out[m][n] = sum_k act[m][k] * B[n][k] ----------------
// TM=128, TN=128, K=2048 in 64 chunks. 4-stage cp.async pipeline, 1 sync/chunk. tf32 outputs.
// S2M=1: out1 = tf32(2*v - I). S2M=0: n<NN -> out1, else out2 (at n-NN), both tf32.
template<int S2M>
__global__ __launch_bounds__(256)
void diffuse_kernel(const float* __restrict__ actT, const float* __restrict__ bTp,
                    float* __restrict__ out1, float* __restrict__ out2)
{
    constexpr int ABYTES = 128 * 128;           // 16KB
    constexpr int STG = ABYTES + 16384;         // 32KB/stage
    extern __shared__ char smem[];
    uint32_t sb = smem_u32(smem);
    int tid = threadIdx.x, lane = tid & 31, wid = tid >> 5;
    int wm = wid >> 1, wn = wid & 1;
    int m0 = blockIdx.y << 7, n0 = blockIdx.x << 7;

    const char* aT = (const char*)(actT + (size_t)m0 * NN);
    const char* bT = (const char*)(bTp  + (size_t)n0 * NN);

    auto load_chunk = [&](int kc, int stg){
        const char* As = aT + (size_t)kc * 128;
        const char* Bs = bT + (size_t)kc * 128;
        uint32_t s = sb + stg * STG;
        #pragma unroll
        for (int i = 0; i < 4; i++){
            int q = tid + (i << 8);
            int row = q >> 3, c = (q & 7) << 4;
            cpa16(s + SWZ((uint32_t)(row*128 + c)), As + (size_t)row*8192 + c);
        }
        #pragma unroll
        for (int i = 0; i < 4; i++){
            int q = tid + (i << 8);
            int row = q >> 3, c = (q & 7) << 4;
            cpa16(s + ABYTES + SWZ((uint32_t)(row*128 + c)), Bs + (size_t)row*8192 + c);
        }
    };

    float acc[2][8][4];
    #pragma unroll
    for (int i = 0; i < 2; i++)
        #pragma unroll
        for (int j = 0; j < 8; j++)
            #pragma unroll
            for (int q = 0; q < 4; q++) acc[i][j][q] = 0.f;

    load_chunk(0, 0); asm volatile("cp.async.commit_group;" ::: "memory");
    load_chunk(1, 1); asm volatile("cp.async.commit_group;" ::: "memory");
    load_chunk(2, 2); asm volatile("cp.async.commit_group;" ::: "memory");

    for (int kc = 0; kc < 64; kc++){
        asm volatile("cp.async.wait_group 2;" ::: "memory");
        __syncthreads();
        uint32_t sA = sb + (kc & 3) * STG, sB = sA + ABYTES;

        uint32_t af[2][2][4], bfr[2][8][2];
        auto load_frags = [&](int s, int buf){
            uint32_t c0 = (uint32_t)(s*32 + ((lane & 3) << 2));
            #pragma unroll
            for (int i = 0; i < 2; i++){
                int row = wm*32 + i*16 + (lane >> 2);
                af[buf][i][0] = lds_u(sA + SWZ((uint32_t)(row*128)     + c0));
                af[buf][i][1] = lds_u(sA + SWZ((uint32_t)((row+8)*128) + c0));
                af[buf][i][2] = lds_u(sA + SWZ((uint32_t)(row*128)     + c0 + 16));
                af[buf][i][3] = lds_u(sA + SWZ((uint32_t)((row+8)*128) + c0 + 16));
            }
            #pragma unroll
            for (int j = 0; j < 8; j++){
                int n = wn*64 + j*8 + (lane >> 2);
                bfr[buf][j][0] = lds_u(sB + SWZ((uint32_t)(n*128) + c0));
                bfr[buf][j][1] = lds_u(sB + SWZ((uint32_t)(n*128) + c0 + 16));
            }
        };

        load_frags(0, 0);
        #pragma unroll
        for (int s = 0; s < 4; s++){
            if (s < 3) load_frags(s + 1, (s + 1) & 1);
            int b = s & 1;
            #pragma unroll
            for (int j = 0; j < 8; j++){
                mma1688(acc[0][j], af[b][0], bfr[b][j][0], bfr[b][j][1]);
                mma1688(acc[1][j], af[b][1], bfr[b][j][0], bfr[b][j][1]);
            }
        }
        if (kc + 3 < 64) load_chunk(kc + 3, (kc + 3) & 3);
        asm volatile("cp.async.commit_group;" ::: "memory");
    }

    float* o; int cb;
    if (S2M || n0 < NN){ o = out1; cb = n0; }
    else { o = out2; cb = n0 - NN; }
    #pragma unroll
    for (int i = 0; i < 2; i++){
        int rowb = m0 + wm*32 + i*16 + (lane >> 2);
        #pragma unroll
        for (int j = 0; j < 8; j++){
            int col = cb + wn*64 + j*8 + (lane & 3)*2;
            #pragma unroll
            for (int h = 0; h < 2; h++){
                int row = rowb + h*8;
                size_t off = (size_t)row * NN + col;
                float2 v; v.x = acc[i][j][h*2]; v.y = acc[i][j][h*2+1];
                if (S2M){
                    v.x = 2.f*v.x - ((row == col)   ? 1.f : 0.f);
                    v.y = 2.f*v.y - ((row == col+1) ? 1.f : 0.f);
                }
                v.x = tf32r(v.x); v.y = tf32r(v.y);
                *(float2*)&o[off] = v;
            }
        }
    }
}

// ---------------- gate/cand MMA kernels ----------------
// zr[o][n] = sum_k Wt[o][k] * F[k][n].  K=384 in 12 chunks of 32. 3-stage pipeline.
// Fs padded to 136 floats/row (k-stride 8 mod 32 -> conflict-free b-frags).
#define FS_PAD 136
#define FS_B (32*FS_PAD*4)

template<int MO>   // 128 = gate, 64 = cand
__device__ __forceinline__ void gc_mma_core(
    const float* const* srcs, const float* Wt, int n0,
    float acc[2][8][4], int lane, int wm, int wn, uint32_t sb)
{
    constexpr int WSB = MO * 144;             // Ws bytes/stage
    constexpr int STG = WSB + FS_B;
    constexpr int NJ = (MO == 128) ? 8 : 4;
    int tid = threadIdx.x;

    auto load_chunk = [&](int kc, int stg){
        uint32_t s = sb + stg * STG;
        const float* wsrc = Wt + kc*32;
        #pragma unroll
        for (int i = 0; i < MO*8/256; i++){
            int q = tid + (i << 8);
            int row = q >> 3, c16 = (q & 7) << 4;
            cpa16(s + (uint32_t)(row*144 + c16), (const char*)(wsrc + (size_t)row*384) + c16);
        }
        const float* fsrc = srcs[kc >> 1] + (size_t)((kc & 1) << 5)*NN + n0;
        #pragma unroll
        for (int i = 0; i < 4; i++){
            int q = tid + (i << 8);
            int row = q >> 5, c16 = (q & 31) << 4;
            cpa16(s + WSB + (uint32_t)(row*(FS_PAD*4) + c16), (const char*)(fsrc + (size_t)row*NN) + c16);
        }
    };

    load_chunk(0, 0); asm volatile("cp.async.commit_group;" ::: "memory");
    load_chunk(1, 1); asm volatile("cp.async.commit_group;" ::: "memory");

    for (int kc = 0; kc < 12; kc++){
        asm volatile("cp.async.wait_group 1;" ::: "memory");
        __syncthreads();
        uint32_t sW = sb + (kc % 3) * STG, sF = sW + WSB;
        #pragma unroll
        for (int s = 0; s < 4; s++){
            int k = s*8 + (lane & 3);
            uint32_t a[2][4];
            #pragma unroll
            for (int i = 0; i < 2; i++){
                int row = wm*32 + i*16 + (lane >> 2);
                a[i][0] = lds_u(sW + (uint32_t)(row*144     + k*4));
                a[i][1] = lds_u(sW + (uint32_t)((row+8)*144 + k*4));
                a[i][2] = lds_u(sW + (uint32_t)(row*144     + (k+4)*4));
                a[i][3] = lds_u(sW + (uint32_t)((row+8)*144 + (k+4)*4));
            }
            #pragma unroll
            for (int j = 0; j < NJ; j++){
                int n = wn*(NJ*8) + j*8 + (lane >> 2);
                uint32_t b0 = lds_u(sF + (uint32_t)(k*(FS_PAD*4)     + n*4));
                uint32_t b1 = lds_u(sF + (uint32_t)((k+4)*(FS_PAD*4) + n*4));
                mma1688(acc[0][j], a[0], b0, b1);
                mma1688(acc[1][j], a[1], b0, b1);
            }
        }
        if (kc + 2 < 12) load_chunk(kc + 2, (kc + 2) % 3);
        asm volatile("cp.async.commit_group;" ::: "memory");
    }
}

__global__ __launch_bounds__(256)
void gate_mma_kernel(const float* __restrict__ bg, int t){
    extern __shared__ char smem[];
    uint32_t sb = smem_u32(smem);
    int tid = threadIdx.x, lane = tid & 31, wid = tid >> 5;
    int wm = wid >> 1, wn = wid & 1;            // wm 0..3 (o), wn 0..1 (n 64)
    int n0 = blockIdx.x << 7, b = blockIdx.y;
    const float* srcs[6] = {
        g_tbuf + T_X   + ((size_t)(b*TT + t))*DD*NN,
        g_tbuf + T_H   + (size_t)b*DD*NN,
        g_tbuf + T_XD1 + ((size_t)(b*TT + t))*DD*NN,
        g_tbuf + T_HD1 + (size_t)b*DD*NN,
        g_tbuf + T_XD2 + ((size_t)(b*TT + t))*DD*NN,
        g_tbuf + T_HD2 + (size_t)b*DD*NN };
    float acc[2][8][4];
    #pragma unroll
    for (int i=0;i<2;i++) for (int j=0;j<8;j++) for (int q=0;q<4;q++) acc[i][j][q]=0.f;
    gc_mma_core<128>(srcs, g_tbuf + T_WG, n0, acc, lane, wm, wn, sb);

    #pragma unroll
    for (int i = 0; i < 2; i++){
        int ob = wm*32 + i*16 + (lane >> 2);
        #pragma unroll
        for (int j = 0; j < 8; j++){
            int n = n0 + wn*64 + j*8 + (lane & 3)*2;
            #pragma unroll
            for (int h = 0; h < 2; h++){
                int o = ob + h*8;
                float2 v; v.x = acc[i][j][h*2] + bg[o]; v.y = acc[i][j][h*2+1] + bg[o];
                v.x = 1.f/(1.f + __expf(-v.x)); v.y = 1.f/(1.f + __expf(-v.y));
                if (o < 64){
                    size_t idx = ((size_t)b*DD + o)*NN + n;
                    float2 hh = *(const float2*)&g_fbuf[O_HF + idx];
                    float2 g; g.x = tf32r(v.x*hh.x); g.y = tf32r(v.y*hh.y);
                    *(float2*)&g_tbuf[T_G + idx] = g;
                } else {
                    *(float2*)&g_fbuf[O_RF + ((size_t)b*DD + (o-64))*NN + n] = v;
                }
            }
        }
    }
}

__global__ __launch_bounds__(256)
void cand_mma_kernel(const float* __restrict__ bc, int t){
    extern __shared__ char smem[];
    uint32_t sb = smem_u32(smem);
    int tid = threadIdx.x, lane = tid & 31, wid = tid >> 5;
    int wm = wid >> 2, wn = wid & 3;            // wm 0..1 (o 32), wn 0..3 (n 32)
    int n0 = blockIdx.x << 7, b = blockIdx.y;
    const float* srcs[6] = {
        g_tbuf + T_X   + ((size_t)(b*TT + t))*DD*NN,
        g_tbuf + T_G   + (size_t)b*DD*NN,
        g_tbuf + T_XD1 + ((size_t)(b*TT + t))*DD*NN,
        g_tbuf + T_GD1 + (size_t)b*DD*NN,
        g_tbuf + T_XD2 + ((size_t)(b*TT + t))*DD*NN,
        g_tbuf + T_GD2 + (size_t)b*DD*NN };
    float acc[2][8][4];
    #pragma unroll
    for (int i=0;i<2;i++) for (int j=0;j<8;j++) for (int q=0;q<4;q++) acc[i][j][q]=0.f;
    gc_mma_core<64>(srcs, g_tbuf + T_WC, n0, acc, lane, wm, wn, sb);

    #pragma unroll
    for (int i = 0; i < 2; i++){
        int ob = wm*32 + i*16 + (lane >> 2);
        #pragma unroll
        for (int j = 0; j < 4; j++){
            int n = n0 + wn*32 + j*8 + (lane & 3)*2;
            #pragma unroll
            for (int h = 0; h < 2; h++){
                int o = ob + h*8;
                size_t idx = ((size_t)b*DD + o)*NN + n;
                float2 hc; hc.x = tanhf(acc[i][j][h*2] + bc[o]); hc.y = tanhf(acc[i][j][h*2+1] + bc[o]);
                float2 r  = *(const float2*)&g_fbuf[O_RF + idx];
                float2 hh = *(const float2*)&g_fbuf[O_HF + idx];
                float2 hn; hn.x = r.x*hh.x + (1.f-r.x)*hc.x; hn.y = r.y*hh.y + (1.f-r.y)*hc.y;
                *(float2*)&g_fbuf[O_HF + idx] = hn;
                float2 ht; ht.x = tf32r(hn.x); ht.y = tf32r(hn.y);
                *(float2*)&g_tbuf[T_H + idx] = ht;
                *(float2*)&g_fbuf[O_ST + (size_t)t*MHN + idx] = hn;
            }
        }
    }
}

// ---------------- prep kernels ----------------
__global__ __launch_bounds__(256) void prep_adj_kernel(const float* __restrict__ adj){
    size_t i = ((size_t)blockIdx.x * 256 + threadIdx.x) * 4;
    float4 v = *(const float4*)&adj[i];
    float4 t; t.x = tf32r(v.x); t.y = tf32r(v.y); t.z = tf32r(v.z); t.w = tf32r(v.w);
    *(float4*)&g_tbuf[T_A + i] = t;
}

__global__ __launch_bounds__(256) void prep_adjT_kernel(const float* __restrict__ adj){
    __shared__ float S[32][33];
    int x0 = blockIdx.x << 5, y0 = blockIdx.y << 5;
    int tx = threadIdx.x & 31, ty = threadIdx.x >> 5;
    #pragma unroll
    for (int i = 0; i < 4; i++)
        S[ty + i*8][tx] = adj[(size_t)(y0 + ty + i*8)*NN + x0 + tx];
    __syncthreads();
    #pragma unroll
    for (int i = 0; i < 4; i++)
        g_tbuf[T_AT + (size_t)(x0 + ty + i*8)*NN + y0 + tx] = tf32r(S[tx][ty + i*8]);
}

// W[384][O] -> Wt[O][384] tf32
__global__ void prep_W_kernel(const float* __restrict__ W, float* __restrict__ Wt, int O){
    int i = blockIdx.x * 256 + threadIdx.x;
    if (i >= 384*O) return;
    int k = i / O, o = i % O;
    Wt[(size_t)o*384 + k] = tf32r(W[i]);
}

// transpose [row][n][d] -> feature-major [row*64+d][n]. WF: also exact fp32.
template<int WF>
__global__ __launch_bounds__(256)
void prep_T_kernel(const float* __restrict__ src, float* __restrict__ dstT,
                   float* __restrict__ dstF){
    __shared__ float S[64][65];
    int n0 = blockIdx.x << 6, rr = blockIdx.y;
    const float* sp = src + ((size_t)rr * NN + n0) * DD;
    #pragma unroll
    for (int i = 0; i < 16; i++){
        int q = threadIdx.x + (i << 8);
        S[q >> 6][q & 63] = sp[(size_t)(q >> 6) * DD + (q & 63)];
    }
    __syncthreads();
    #pragma unroll
    for (int i = 0; i < 16; i++){
        int q = threadIdx.x + (i << 8);
        int d = q >> 6, nl = q & 63;
        float v = S[nl][d];
        size_t off = ((size_t)rr * DD + d) * NN + n0 + nl;
        dstT[off] = tf32r(v);
        if (WF) dstF[off] = v;
    }
}

// ---------------- output assembly ----------------
__global__ __launch_bounds__(256)
void final_out_kernel(const float* __restrict__ x, float* __restrict__ out){
    __shared__ float S[64][65];
    int n0 = blockIdx.x << 6, bt = blockIdx.y;
    int b = bt / TT, t = bt % TT;
    const float* st = g_fbuf + O_ST + (size_t)t*MHN + (size_t)b*DD*NN;
    #pragma unroll
    for (int i = 0; i < 16; i++){
        int q = threadIdx.x + (i << 8);
        int d = q >> 6, nl = q & 63;
        S[d][nl] = st[(size_t)d*NN + n0 + nl];
    }
    __syncthreads();
    #pragma unroll
    for (int i = 0; i < 16; i++){
        int q = threadIdx.x + (i << 8);
        int nl = q >> 6, d = q & 63;
        size_t off = ((size_t)bt*NN + n0 + nl)*DD + d;
        out[off] = x[off] + S[d][nl];
    }
}

__global__ __launch_bounds__(256)
void last_out_kernel(float* __restrict__ outL){
    __shared__ float S[64][65];
    int n0 = blockIdx.x << 6, b = blockIdx.y;
    const float* hp = g_fbuf + O_HF + (size_t)b*DD*NN;
    #pragma unroll
    for (int i = 0; i < 16; i++){
        int q = threadIdx.x + (i << 8);
        int d = q >> 6, nl = q & 63;
        S[d][nl] = hp[(size_t)d*NN + n0 + nl];
    }
    __syncthreads();
    #pragma unroll
    for (int i = 0; i < 16; i++){
        int q = threadIdx.x + (i << 8);
        int nl = q >> 6, d = q & 63;
        outL[((size_t)b*NN + n0 + nl)*DD + d] = S[d][nl];
    }
}

// ---------------- launch ----------------
extern "C" void kernel_launch(void* const* d_in, const int* in_sizes, int n_in,
                              void* d_out, int out_size) {
    const float* x   = (const float*)d_in[0];
    const float* h0  = (const float*)d_in[1];
    const float* adj = (const float*)d_in[2];
    const float* Wg  = (const float*)d_in[3];
    const float* bg  = (const float*)d_in[4];
    const float* Wc  = (const float*)d_in[5];
    const float* bc  = (const float*)d_in[6];
    float* out = (float*)d_out;

    void *pf, *pt;
    cudaGetSymbolAddress(&pf, g_fbuf);
    cudaGetSymbolAddress(&pt, g_tbuf);
    float* F = (float*)pf;
    float* T = (float*)pt;

    const int DSM   = 4 * 32768;                    // diffuse: 4 x 32KB
    const int GSM   = 3 * (128*144 + FS_B);         // gate:   107,520
    const int CSM   = 3 * (64*144  + FS_B);         // cand:    79,872
    cudaFuncSetAttribute(diffuse_kernel<0>, cudaFuncAttributeMaxDynamicSharedMemorySize, DSM);
    cudaFuncSetAttribute(diffuse_kernel<1>, cudaFuncAttributeMaxDynamicSharedMemorySize, DSM);
    cudaFuncSetAttribute(gate_mma_kernel,   cudaFuncAttributeMaxDynamicSharedMemorySize, GSM);
    cudaFuncSetAttribute(cand_mma_kernel,   cudaFuncAttributeMaxDynamicSharedMemorySize, CSM);

    prep_adj_kernel<<<(int)(NN2/1024), 256>>>(adj);
    prep_adjT_kernel<<<dim3(NN/32, NN/32), 256>>>(adj);
    prep_W_kernel<<<(384*128+255)/256, 256>>>(Wg, T+T_WG, 128);
    prep_W_kernel<<<(384*64+255)/256, 256>>>(Wc, T+T_WC, 64);
    prep_T_kernel<0><<<dim3(NN/64, BB*TT), 256>>>(x,  T+T_X, nullptr);
    prep_T_kernel<1><<<dim3(NN/64, BB),    256>>>(h0, T+T_H, F+O_HF);

    // S2' = tf32(2*A@A - I)
    diffuse_kernel<1><<<dim3(16,16),256,DSM>>>(T+T_A, T+T_AT, T+T_S2, nullptr);
    // x diffusions vs stacked [A';S2']
    diffuse_kernel<0><<<dim3(32,48),256,DSM>>>(T+T_X, T+T_A, T+T_XD1, T+T_XD2);

    for (int t = 0; t < TT; t++){
        diffuse_kernel<0><<<dim3(32,4),256,DSM>>>(T+T_H, T+T_A, T+T_HD1, T+T_HD2);
        gate_mma_kernel<<<dim3(16,8),256,GSM>>>(bg, t);
        diffuse_kernel<0><<<dim3(32,4),256,DSM>>>(T+T_G, T+T_A, T+T_GD1, T+T_GD2);
        cand_mma_kernel<<<dim3(16,8),256,CSM>>>(bc, t);
    }

    final_out_kernel<<<dim3(NN/64, BB*TT), 256>>>(x, out);
    last_out_kernel<<<dim3(NN/64, BB), 256>>>(out + MXN);
}

// round 10
// speedup vs baseline: 4.5864x; 1.1271x over previous
#include <cuda_runtime.h>
#include <cstdint>
#include <cstddef>

#define NN 2048
#define BB 8
#define TT 12
#define DD 64
#define MX 6144
#define MH 512
static constexpr size_t MXN = (size_t)MX*NN;
static constexpr size_t MHN = (size_t)MH*NN;
static constexpr size_t NN2 = (size_t)NN*NN;

// ---- exact fp32 scratch ----
static constexpr size_t O_ST=0, O_HF=O_ST+12*MHN, O_RF=O_HF+MHN, NFB=O_RF+MHN;
// ---- tf32-rounded scratch (T_S2 MUST follow T_A: stacked [A';S2']) ----
static constexpr size_t T_A=0, T_S2=T_A+NN2, T_AT=T_S2+NN2, T_X=T_AT+NN2,
 T_XD1=T_X+MXN, T_XD2=T_XD1+MXN,
 T_H=T_XD2+MXN, T_HD1=T_H+MHN, T_HD2=T_HD1+MHN,
 T_G=T_HD2+MHN, T_GD1=T_G+MHN, T_GD2=T_GD1+MHN,
 T_WG=T_GD2+MHN, T_WC=T_WG+384*128, NTB=T_WC+384*64;

__device__ float g_fbuf[NFB];
__device__ float g_tbuf[NTB];

// ---------------- helpers ----------------
__device__ __forceinline__ uint32_t smem_u32(const void* p){
    uint32_t a;
    asm("{ .reg .u64 t; cvta.to.shared.u64 t, %1; cvt.u32.u64 %0, t; }" : "=r"(a) : "l"(p));
    return a;
}
#define SWZ(x) ((x) ^ (((x) >> 3) & 0x70))

__device__ __forceinline__ float tf32r(float v){
    uint32_t r; asm("cvt.rna.tf32.f32 %0, %1;" : "=r"(r) : "f"(v));
    return __uint_as_float(r);
}
__device__ __forceinline__ uint32_t lds_u(uint32_t a){
    uint32_t v; asm volatile("ld.shared.b32 %0, [%1];" : "=r"(v) : "r"(a)); return v;
}
__device__ __forceinline__ void cpa16(uint32_t d, const void* s){
    asm volatile("cp.async.cg.shared.global [%0], [%1], 16;" :: "r"(d), "l"(s) : "memory");
}
__device__ __forceinline__ void mma1688(float* c, const uint32_t* a, uint32_t b0, uint32_t b1){
    asm volatile("mma.sync.aligned.m16n8k8.row.col.f32.tf32.tf32.f32 "
        "{%0,%1,%2,%3}, {%4,%5,%6,%7}, {%8,%9}, {%0,%1,%2,%3};"
        : "+f"(c[0]), "+f"(c[1]), "+f"(c[2]), "+f"(c[3])
        : "r"(a[0]), "r"(a[1]), "r"(a[2]), "r"(a[3]), "r"(b0), "r"(b1));
}

// ---------------- diffusion GEMM (tf32): out[m][n] = sum_k act[m][k] * B[n][k] ----------------
// TM=128, TN=128, K=2048 in 64 chunks of 32 floats. 6 smem stages, chunks committed in PAIRS:
// one wait_group + one __syncthreads per TWO chunks. tf32 outputs.
// S2M=1: out1 = tf32(2*v - I). S2M=0: n<NN -> out1, else out2 (at n-NN).
template<int S2M>
__global__ __launch_bounds__(256)
void diffuse_kernel(const float* __restrict__ actT, const float* __restrict__ bTp,
                    float* __restrict__ out1, float* __restrict__ out2)
{
    constexpr int ABYTES = 128 * 128;           // 16KB
    constexpr int STG = ABYTES + 16384;         // 32KB/stage
    extern __shared__ char smem[];
    uint32_t sb = smem_u32(smem);
    int tid = threadIdx.x, lane = tid & 31, wid = tid >> 5;
    int wm = wid >> 1, wn = wid & 1;
    int m0 = blockIdx.y << 7, n0 = blockIdx.x << 7;

    const char* aT = (const char*)(actT + (size_t)m0 * NN);
    const char* bT = (const char*)(bTp  + (size_t)n0 * NN);

    auto load_chunk = [&](int kc, int stg){
        const char* As = aT + (size_t)kc * 128;
        const char* Bs = bT + (size_t)kc * 128;
        uint32_t s = sb + stg * STG;
        #pragma unroll
        for (int i = 0; i < 4; i++){
            int q = tid + (i << 8);
            int row = q >> 3, c = (q & 7) << 4;
            cpa16(s + SWZ((uint32_t)(row*128 + c)), As + (size_t)row*8192 + c);
        }
        #pragma unroll
        for (int i = 0; i < 4; i++){
            int q = tid + (i << 8);
            int row = q >> 3, c = (q & 7) << 4;
            cpa16(s + ABYTES + SWZ((uint32_t)(row*128 + c)), Bs + (size_t)row*8192 + c);
        }
    };

    float acc[2][8][4];
    #pragma unroll
    for (int i = 0; i < 2; i++)
        #pragma unroll
        for (int j = 0; j < 8; j++)
            #pragma unroll
            for (int q = 0; q < 4; q++) acc[i][j][q] = 0.f;

    // prologue: 4 chunks in 2 groups
    load_chunk(0, 0); load_chunk(1, 1);
    asm volatile("cp.async.commit_group;" ::: "memory");
    load_chunk(2, 2); load_chunk(3, 3);
    asm volatile("cp.async.commit_group;" ::: "memory");

    uint32_t af[2][2][4], bfr[2][8][2];
    auto load_frags = [&](uint32_t stgBase, int s, int buf){
        uint32_t sA = stgBase, sB = stgBase + ABYTES;
        uint32_t c0 = (uint32_t)(s*32 + ((lane & 3) << 2));
        #pragma unroll
        for (int i = 0; i < 2; i++){
            int row = wm*32 + i*16 + (lane >> 2);
            af[buf][i][0] = lds_u(sA + SWZ((uint32_t)(row*128)     + c0));
            af[buf][i][1] = lds_u(sA + SWZ((uint32_t)((row+8)*128) + c0));
            af[buf][i][2] = lds_u(sA + SWZ((uint32_t)(row*128)     + c0 + 16));
            af[buf][i][3] = lds_u(sA + SWZ((uint32_t)((row+8)*128) + c0 + 16));
        }
        #pragma unroll
        for (int j = 0; j < 8; j++){
            int n = wn*64 + j*8 + (lane >> 2);
            bfr[buf][j][0] = lds_u(sB + SWZ((uint32_t)(n*128) + c0));
            bfr[buf][j][1] = lds_u(sB + SWZ((uint32_t)(n*128) + c0 + 16));
        }
    };

    for (int kc = 0; kc < 64; kc += 2){
        asm volatile("cp.async.wait_group 1;" ::: "memory");
        __syncthreads();
        uint32_t st0 = sb + (kc % 6) * STG;
        uint32_t st1 = sb + ((kc + 1) % 6) * STG;

        load_frags(st0, 0, 0);
        #pragma unroll
        for (int s = 0; s < 8; s++){
            if (s < 7){
                int sn = s + 1;
                load_frags((sn < 4) ? st0 : st1, sn & 3, sn & 1);
            }
            int b = s & 1;
            #pragma unroll
            for (int j = 0; j < 8; j++){
                mma1688(acc[0][j], af[b][0], bfr[b][j][0], bfr[b][j][1]);
                mma1688(acc[1][j], af[b][1], bfr[b][j][0], bfr[b][j][1]);
            }
        }
        if (kc + 4 < 64){
            load_chunk(kc + 4, (kc + 4) % 6);
            load_chunk(kc + 5, (kc + 5) % 6);
        }
        asm volatile("cp.async.commit_group;" ::: "memory");
    }

    float* o; int cb;
    if (S2M || n0 < NN){ o = out1; cb = n0; }
    else { o = out2; cb = n0 - NN; }
    #pragma unroll
    for (int i = 0; i < 2; i++){
        int rowb = m0 + wm*32 + i*16 + (lane >> 2);
        #pragma unroll
        for (int j = 0; j < 8; j++){
            int col = cb + wn*64 + j*8 + (lane & 3)*2;
            #pragma unroll
            for (int h = 0; h < 2; h++){
                int row = rowb + h*8;
                size_t off = (size_t)row * NN + col;
                float2 v; v.x = acc[i][j][h*2]; v.y = acc[i][j][h*2+1];
                if (S2M){
                    v.x = 2.f*v.x - ((row == col)   ? 1.f : 0.f);
                    v.y = 2.f*v.y - ((row == col+1) ? 1.f : 0.f);
                }
                v.x = tf32r(v.x); v.y = tf32r(v.y);
                *(float2*)&o[off] = v;
            }
        }
    }
}

// ---------------- gate/cand MMA kernels ----------------
#define FS_PAD 136
#define FS_B (32*FS_PAD*4)

template<int MO>   // 128 = gate, 64 = cand
__device__ __forceinline__ void gc_mma_core(
    const float* const* srcs, const float* Wt, int n0,
    float acc[2][8][4], int lane, int wm, int wn, uint32_t sb)
{
    constexpr int WSB = MO * 144;
    constexpr int STG = WSB + FS_B;
    constexpr int NJ = (MO == 128) ? 8 : 4;
    int tid = threadIdx.x;

    auto load_chunk = [&](int kc, int stg){
        uint32_t s = sb + stg * STG;
        const float* wsrc = Wt + kc*32;
        #pragma unroll
        for (int i = 0; i < MO*8/256; i++){
            int q = tid + (i << 8);
            int row = q >> 3, c16 = (q & 7) << 4;
            cpa16(s + (uint32_t)(row*144 + c16), (const char*)(wsrc + (size_t)row*384) + c16);
        }
        const float* fsrc = srcs[kc >> 1] + (size_t)((kc & 1) << 5)*NN + n0;
        #pragma unroll
        for (int i = 0; i < 4; i++){
            int q = tid + (i << 8);
            int row = q >> 5, c16 = (q & 31) << 4;
            cpa16(s + WSB + (uint32_t)(row*(FS_PAD*4) + c16), (const char*)(fsrc + (size_t)row*NN) + c16);
        }
    };

    load_chunk(0, 0); asm volatile("cp.async.commit_group;" ::: "memory");
    load_chunk(1, 1); asm volatile("cp.async.commit_group;" ::: "memory");

    for (int kc = 0; kc < 12; kc++){
        asm volatile("cp.async.wait_group 1;" ::: "memory");
        __syncthreads();
        uint32_t sW = sb + (kc % 3) * STG, sF = sW + WSB;
        #pragma unroll
        for (int s = 0; s < 4; s++){
            int k = s*8 + (lane & 3);
            uint32_t a[2][4];
            #pragma unroll
            for (int i = 0; i < 2; i++){
                int row = wm*32 + i*16 + (lane >> 2);
                a[i][0] = lds_u(sW + (uint32_t)(row*144     + k*4));
                a[i][1] = lds_u(sW + (uint32_t)((row+8)*144 + k*4));
                a[i][2] = lds_u(sW + (uint32_t)(row*144     + (k+4)*4));
                a[i][3] = lds_u(sW + (uint32_t)((row+8)*144 + (k+4)*4));
            }
            #pragma unroll
            for (int j = 0; j < NJ; j++){
                int n = wn*(NJ*8) + j*8 + (lane >> 2);
                uint32_t b0 = lds_u(sF + (uint32_t)(k*(FS_PAD*4)     + n*4));
                uint32_t b1 = lds_u(sF + (uint32_t)((k+4)*(FS_PAD*4) + n*4));
                mma1688(acc[0][j], a[0], b0, b1);
                mma1688(acc[1][j], a[1], b0, b1);
            }
        }
        if (kc + 2 < 12) load_chunk(kc + 2, (kc + 2) % 3);
        asm volatile("cp.async.commit_group;" ::: "memory");
    }
}

__global__ __launch_bounds__(256)
void gate_mma_kernel(const float* __restrict__ bg, int t){
    extern __shared__ char smem[];
    uint32_t sb = smem_u32(smem);
    int tid = threadIdx.x, lane = tid & 31, wid = tid >> 5;
    int wm = wid >> 1, wn = wid & 1;
    int n0 = blockIdx.x << 7, b = blockIdx.y;
    const float* srcs[6] = {
        g_tbuf + T_X   + ((size_t)(b*TT + t))*DD*NN,
        g_tbuf + T_H   + (size_t)b*DD*NN,
        g_tbuf + T_XD1 + ((size_t)(b*TT + t))*DD*NN,
        g_tbuf + T_HD1 + (size_t)b*DD*NN,
        g_tbuf + T_XD2 + ((size_t)(b*TT + t))*DD*NN,
        g_tbuf + T_HD2 + (size_t)b*DD*NN };
    float acc[2][8][4];
    #pragma unroll
    for (int i=0;i<2;i++) for (int j=0;j<8;j++) for (int q=0;q<4;q++) acc[i][j][q]=0.f;
    gc_mma_core<128>(srcs, g_tbuf + T_WG, n0, acc, lane, wm, wn, sb);

    #pragma unroll
    for (int i = 0; i < 2; i++){
        int ob = wm*32 + i*16 + (lane >> 2);
        #pragma unroll
        for (int j = 0; j < 8; j++){
            int n = n0 + wn*64 + j*8 + (lane & 3)*2;
            #pragma unroll
            for (int h = 0; h < 2; h++){
                int o = ob + h*8;
                float2 v; v.x = acc[i][j][h*2] + bg[o]; v.y = acc[i][j][h*2+1] + bg[o];
                v.x = 1.f/(1.f + __expf(-v.x)); v.y = 1.f/(1.f + __expf(-v.y));
                if (o < 64){
                    size_t idx = ((size_t)b*DD + o)*NN + n;
                    float2 hh = *(const float2*)&g_fbuf[O_HF + idx];
                    float2 g; g.x = tf32r(v.x*hh.x); g.y = tf32r(v.y*hh.y);
                    *(float2*)&g_tbuf[T_G + idx] = g;
                } else {
                    *(float2*)&g_fbuf[O_RF + ((size_t)b*DD + (o-64))*NN + n] = v;
                }
            }
        }
    }
}

__global__ __launch_bounds__(256)
void cand_mma_kernel(const float* __restrict__ bc, int t){
    extern __shared__ char smem[];
    uint32_t sb = smem_u32(smem);
    int tid = threadIdx.x, lane = tid & 31, wid = tid >> 5;
    int wm = wid >> 2, wn = wid & 3;
    int n0 = blockIdx.x << 7, b = blockIdx.y;
    const float* srcs[6] = {
        g_tbuf + T_X   + ((size_t)(b*TT + t))*DD*NN,
        g_tbuf + T_G   + (size_t)b*DD*NN,
        g_tbuf + T_XD1 + ((size_t)(b*TT + t))*DD*NN,
        g_tbuf + T_GD1 + (size_t)b*DD*NN,
        g_tbuf + T_XD2 + ((size_t)(b*TT + t))*DD*NN,
        g_tbuf + T_GD2 + (size_t)b*DD*NN };
    float acc[2][8][4];
    #pragma unroll
    for (int i=0;i<2;i++) for (int j=0;j<8;j++) for (int q=0;q<4;q++) acc[i][j][q]=0.f;
    gc_mma_core<64>(srcs, g_tbuf + T_WC, n0, acc, lane, wm, wn, sb);

    #pragma unroll
    for (int i = 0; i < 2; i++){
        int ob = wm*32 + i*16 + (lane >> 2);
        #pragma unroll
        for (int j = 0; j < 4; j++){
            int n = n0 + wn*32 + j*8 + (lane & 3)*2;
            #pragma unroll
            for (int h = 0; h < 2; h++){
                int o = ob + h*8;
                size_t idx = ((size_t)b*DD + o)*NN + n;
                float2 hc; hc.x = tanhf(acc[i][j][h*2] + bc[o]); hc.y = tanhf(acc[i][j][h*2+1] + bc[o]);
                float2 r  = *(const float2*)&g_fbuf[O_RF + idx];
                float2 hh = *(const float2*)&g_fbuf[O_HF + idx];
                float2 hn; hn.x = r.x*hh.x + (1.f-r.x)*hc.x; hn.y = r.y*hh.y + (1.f-r.y)*hc.y;
                *(float2*)&g_fbuf[O_HF + idx] = hn;
                float2 ht; ht.x = tf32r(hn.x); ht.y = tf32r(hn.y);
                *(float2*)&g_tbuf[T_H + idx] = ht;
                *(float2*)&g_fbuf[O_ST + (size_t)t*MHN + idx] = hn;
            }
        }
    }
}

// ---------------- prep kernels ----------------
__global__ __launch_bounds__(256) void prep_adj_kernel(const float* __restrict__ adj){
    size_t i = ((size_t)blockIdx.x * 256 + threadIdx.x) * 4;
    float4 v = *(const float4*)&adj[i];
    float4 t; t.x = tf32r(v.x); t.y = tf32r(v.y); t.z = tf32r(v.z); t.w = tf32r(v.w);
    *(float4*)&g_tbuf[T_A + i] = t;
}

__global__ __launch_bounds__(256) void prep_adjT_kernel(const float* __restrict__ adj){
    __shared__ float S[32][33];
    int x0 = blockIdx.x << 5, y0 = blockIdx.y << 5;
    int tx = threadIdx.x & 31, ty = threadIdx.x >> 5;
    #pragma unroll
    for (int i = 0; i < 4; i++)
        S[ty + i*8][tx] = adj[(size_t)(y0 + ty + i*8)*NN + x0 + tx];
    __syncthreads();
    #pragma unroll
    for (int i = 0; i < 4; i++)
        g_tbuf[T_AT + (size_t)(x0 + ty + i*8)*NN + y0 + tx] = tf32r(S[tx][ty + i*8]);
}

__global__ void prep_W_kernel(const float* __restrict__ W, float* __restrict__ Wt, int O){
    int i = blockIdx.x * 256 + threadIdx.x;
    if (i >= 384*O) return;
    int k = i / O, o = i % O;
    Wt[(size_t)o*384 + k] = tf32r(W[i]);
}

template<int WF>
__global__ __launch_bounds__(256)
void prep_T_kernel(const float* __restrict__ src, float* __restrict__ dstT,
                   float* __restrict__ dstF){
    __shared__ float S[64][65];
    int n0 = blockIdx.x << 6, rr = blockIdx.y;
    const float* sp = src + ((size_t)rr * NN + n0) * DD;
    #pragma unroll
    for (int i = 0; i < 16; i++){
        int q = threadIdx.x + (i << 8);
        S[q >> 6][q & 63] = sp[(size_t)(q >> 6) * DD + (q & 63)];
    }
    __syncthreads();
    #pragma unroll
    for (int i = 0; i < 16; i++){
        int q = threadIdx.x + (i << 8);
        int d = q >> 6, nl = q & 63;
        float v = S[nl][d];
        size_t off = ((size_t)rr * DD + d) * NN + n0 + nl;
        dstT[off] = tf32r(v);
        if (WF) dstF[off] = v;
    }
}

// ---------------- output assembly ----------------
__global__ __launch_bounds__(256)
void final_out_kernel(const float* __restrict__ x, float* __restrict__ out){
    __shared__ float S[64][65];
    int n0 = blockIdx.x << 6, bt = blockIdx.y;
    int b = bt / TT, t = bt % TT;
    const float* st = g_fbuf + O_ST + (size_t)t*MHN + (size_t)b*DD*NN;
    #pragma unroll
    for (int i = 0; i < 16; i++){
        int q = threadIdx.x + (i << 8);
        int d = q >> 6, nl = q & 63;
        S[d][nl] = st[(size_t)d*NN + n0 + nl];
    }
    __syncthreads();
    #pragma unroll
    for (int i = 0; i < 16; i++){
        int q = threadIdx.x + (i << 8);
        int nl = q >> 6, d = q & 63;
        size_t off = ((size_t)bt*NN + n0 + nl)*DD + d;
        out[off] = x[off] + S[d][nl];
    }
}

__global__ __launch_bounds__(256)
void last_out_kernel(float* __restrict__ outL){
    __shared__ float S[64][65];
    int n0 = blockIdx.x << 6, b = blockIdx.y;
    const float* hp = g_fbuf + O_HF + (size_t)b*DD*NN;
    #pragma unroll
    for (int i = 0; i < 16; i++){
        int q = threadIdx.x + (i << 8);
        int d = q >> 6, nl = q & 63;
        S[d][nl] = hp[(size_t)d*NN + n0 + nl];
    }
    __syncthreads();
    #pragma unroll
    for (int i = 0; i < 16; i++){
        int q = threadIdx.x + (i << 8);
        int nl = q >> 6, d = q & 63;
        outL[((size_t)b*NN + n0 + nl)*DD + d] = S[d][nl];
    }
}

// ---------------- launch ----------------
extern "C" void kernel_launch(void* const* d_in, const int* in_sizes, int n_in,
                              void* d_out, int out_size) {
    const float* x   = (const float*)d_in[0];
    const float* h0  = (const float*)d_in[1];
    const float* adj = (const float*)d_in[2];
    const float* Wg  = (const float*)d_in[3];
    const float* bg  = (const float*)d_in[4];
    const float* Wc  = (const float*)d_in[5];
    const float* bc  = (const float*)d_in[6];
    float* out = (float*)d_out;

    void *pf, *pt;
    cudaGetSymbolAddress(&pf, g_fbuf);
    cudaGetSymbolAddress(&pt, g_tbuf);
    float* F = (float*)pf;
    float* T = (float*)pt;

    const int DSM   = 6 * 32768;                    // diffuse: 6 x 32KB = 196608
    const int GSM   = 3 * (128*144 + FS_B);
    const int CSM   = 3 * (64*144  + FS_B);
    cudaFuncSetAttribute(diffuse_kernel<0>, cudaFuncAttributeMaxDynamicSharedMemorySize, DSM);
    cudaFuncSetAttribute(diffuse_kernel<1>, cudaFuncAttributeMaxDynamicSharedMemorySize, DSM);
    cudaFuncSetAttribute(gate_mma_kernel,   cudaFuncAttributeMaxDynamicSharedMemorySize, GSM);
    cudaFuncSetAttribute(cand_mma_kernel,   cudaFuncAttributeMaxDynamicSharedMemorySize, CSM);

    prep_adj_kernel<<<(int)(NN2/1024), 256>>>(adj);
    prep_adjT_kernel<<<dim3(NN/32, NN/32), 256>>>(adj);
    prep_W_kernel<<<(384*128+255)/256, 256>>>(Wg, T+T_WG, 128);
    prep_W_kernel<<<(384*64+255)/256, 256>>>(Wc, T+T_WC, 64);
    prep_T_kernel<0><<<dim3(NN/64, BB*TT), 256>>>(x,  T+T_X, nullptr);
    prep_T_kernel<1><<<dim3(NN/64, BB),    256>>>(h0, T+T_H, F+O_HF);

    // S2' = tf32(2*A@A - I)
    diffuse_kernel<1><<<dim3(16,16),256,DSM>>>(T+T_A, T+T_AT, T+T_S2, nullptr);
    // x diffusions vs stacked [A';S2']
    diffuse_kernel<0><<<dim3(32,48),256,DSM>>>(T+T_X, T+T_A, T+T_XD1, T+T_XD2);

    for (int t = 0; t < TT; t++){
        diffuse_kernel<0><<<dim3(32,4),256,DSM>>>(T+T_H, T+T_A, T+T_HD1, T+T_HD2);
        gate_mma_kernel<<<dim3(16,8),256,GSM>>>(bg, t);
        diffuse_kernel<0><<<dim3(32,4),256,DSM>>>(T+T_G, T+T_A, T+T_GD1, T+T_GD2);
        cand_mma_kernel<<<dim3(16,8),256,CSM>>>(bc, t);
    }

    final_out_kernel<<<dim3(NN/64, BB*TT), 256>>>(x, out);
    last_out_kernel<<<dim3(NN/64, BB), 256>>>(out + MXN);
}